// round 5
// baseline (speedup 1.0000x reference)
#include <cuda_runtime.h>
#include <cstdint>
#include <stdint.h>
#include <math.h>

// Problem constants (fixed by the dataset)
#define TSEQ   2048
#define DDIM   4096
#define NQ     32
#define NKV    8
#define HD     128
#define NSLOTS 32768
#define QKVC   6144   // 32*128 + 8*128 + 8*128

// Converted-weight offsets (elements)
#define WQ_ELEMS ((size_t)NQ  * DDIM * HD)   // 16.78M
#define WK_ELEMS ((size_t)NKV * DDIM * HD)   // 4.19M
#define WO_ELEMS ((size_t)DDIM * DDIM)       // 16.78M
#define WQ_OFF   ((size_t)0)
#define WK_OFF   (WQ_OFF + WQ_ELEMS)
#define WV_OFF   (WK_OFF + WK_ELEMS)
#define WO_OFF   (WV_OFF + WK_ELEMS)

// ---------------- scratch (static device allocations; no cudaMalloc) -------
__device__ float    g_QKV[(size_t)TSEQ * QKVC];      // [t][6144]
__device__ float    g_Q  [(size_t)NQ  * TSEQ * HD];  // [n][t][h]
__device__ float    g_K  [(size_t)NKV * TSEQ * HD];  // [kh][t][h]
__device__ float    g_V  [(size_t)NKV * TSEQ * HD];  // [kh][t][h]
__device__ unsigned g_A2 [(size_t)TSEQ * DDIM];      // [t][n*128+h] tf32 bits
__device__ unsigned g_W  [WO_OFF + WO_ELEMS];        // wq|wk|wv|wo tf32 bits
__device__ unsigned g_Xt [(size_t)TSEQ * DDIM];      // x tf32 bits

// ---------------- tf32 mma helpers -----------------------------------------
__device__ __forceinline__ unsigned f2tf(float x) {
    unsigned r;
    asm("cvt.rna.tf32.f32 %0, %1;" : "=r"(r) : "f"(x));
    return r;
}

__device__ __forceinline__ void mma_tf32(float* d, const unsigned* a,
                                         const unsigned* b) {
    asm volatile(
        "mma.sync.aligned.m16n8k8.row.col.f32.tf32.tf32.f32 "
        "{%0,%1,%2,%3}, {%4,%5,%6,%7}, {%8,%9}, {%0,%1,%2,%3};"
        : "+f"(d[0]), "+f"(d[1]), "+f"(d[2]), "+f"(d[3])
        : "r"(a[0]), "r"(a[1]), "r"(a[2]), "r"(a[3]), "r"(b[0]), "r"(b[1]));
}

__device__ __forceinline__ void cp16(unsigned smem, const void* g) {
    asm volatile("cp.async.cg.shared.global [%0], [%1], 16;\n"
                 :: "r"(smem), "l"(g));
}

// ---------------- prep: fp32 -> tf32 bits (elementwise) --------------------
__global__ __launch_bounds__(256) void k_cvt_tf32(
    const float4* __restrict__ in, uint4* __restrict__ out, int n4)
{
    int i = blockIdx.x * 256 + threadIdx.x;
    if (i < n4) {
        float4 v = in[i];
        uint4 o = {f2tf(v.x), f2tf(v.y), f2tf(v.z), f2tf(v.w)};
        out[i] = o;
    }
}

// ---------------- 128x128 tf32 tensor-core GEMM (pre-converted operands) ---
// A row-major tf32-bits [.., lda]; B row-major tf32-bits [Kdim, ldb].
// 256 threads (8 warps 2x4). Kdim % 16 == 0.
__device__ __forceinline__ void gemm_mma128_tf(
    const unsigned* __restrict__ A, int lda,
    const unsigned* __restrict__ B, int ldb,
    float* __restrict__ C, int ldc,
    int Kdim, int rowBase)
{
    __shared__ unsigned As[2][128][20];   // pad 20
    __shared__ unsigned Bs[2][16][136];   // pad 136

    const int tid  = threadIdx.x;
    const int lane = tid & 31;
    const int warp = tid >> 5;
    const int wM   = warp >> 2;
    const int wN   = warp & 3;
    const int g    = lane >> 2;
    const int t    = lane & 3;

    const int ar = tid >> 2, ac = (tid & 3) << 2;
    const int br = tid >> 5, bc = (tid & 31) << 2;

    const unsigned* Ab = A + (size_t)rowBase * lda;

    float acc[4][4][4];
#pragma unroll
    for (int mt = 0; mt < 4; mt++)
#pragma unroll
        for (int nt = 0; nt < 4; nt++)
#pragma unroll
            for (int i = 0; i < 4; i++) acc[mt][nt][i] = 0.f;

    const unsigned sA0 = (unsigned)__cvta_generic_to_shared(&As[0][0][0]);
    const unsigned sB0 = (unsigned)__cvta_generic_to_shared(&Bs[0][0][0]);

    {
        cp16(sA0 + (unsigned)((ar)      * 20 + ac) * 4u, Ab + (size_t)ar * lda + ac);
        cp16(sA0 + (unsigned)((ar + 64) * 20 + ac) * 4u, Ab + (size_t)(ar + 64) * lda + ac);
        cp16(sB0 + (unsigned)((br)      * 136 + bc) * 4u, B + (size_t)br * ldb + bc);
        cp16(sB0 + (unsigned)((br + 8)  * 136 + bc) * 4u, B + (size_t)(br + 8) * ldb + bc);
        asm volatile("cp.async.commit_group;");
    }

    const int niter = Kdim >> 4;
    for (int it = 0; it < niter; it++) {
        if (it + 1 < niter) {
            const int k0 = (it + 1) << 4;
            const unsigned stA = sA0 + (unsigned)((it + 1) & 1) * (unsigned)(128 * 20 * 4);
            const unsigned stB = sB0 + (unsigned)((it + 1) & 1) * (unsigned)(16 * 136 * 4);
            cp16(stA + (unsigned)((ar)      * 20 + ac) * 4u, Ab + (size_t)ar * lda + k0 + ac);
            cp16(stA + (unsigned)((ar + 64) * 20 + ac) * 4u, Ab + (size_t)(ar + 64) * lda + k0 + ac);
            cp16(stB + (unsigned)((br)      * 136 + bc) * 4u, B + (size_t)(k0 + br) * ldb + bc);
            cp16(stB + (unsigned)((br + 8)  * 136 + bc) * 4u, B + (size_t)(k0 + br + 8) * ldb + bc);
        }
        asm volatile("cp.async.commit_group;");
        asm volatile("cp.async.wait_group 1;");
        __syncthreads();

        const int st = it & 1;
#pragma unroll
        for (int ks = 0; ks < 2; ks++) {
            unsigned af[4][4], bf[4][2];
#pragma unroll
            for (int mt = 0; mt < 4; mt++) {
                const unsigned* p = &As[st][wM * 64 + mt * 16 + g][ks * 8 + t];
                af[mt][0] = p[0];
                af[mt][1] = p[8 * 20];
                af[mt][2] = p[4];
                af[mt][3] = p[8 * 20 + 4];
            }
#pragma unroll
            for (int nt = 0; nt < 4; nt++) {
                bf[nt][0] = Bs[st][ks * 8 + t    ][wN * 32 + nt * 8 + g];
                bf[nt][1] = Bs[st][ks * 8 + t + 4][wN * 32 + nt * 8 + g];
            }
#pragma unroll
            for (int mt = 0; mt < 4; mt++)
#pragma unroll
                for (int nt = 0; nt < 4; nt++)
                    mma_tf32(acc[mt][nt], af[mt], bf[nt]);
        }
        __syncthreads();
    }

#pragma unroll
    for (int mt = 0; mt < 4; mt++) {
#pragma unroll
        for (int nt = 0; nt < 4; nt++) {
            const int r0 = rowBase + wM * 64 + mt * 16 + g;
            const int c0 = wN * 32 + nt * 8 + 2 * t;
            float2 v0 = {acc[mt][nt][0], acc[mt][nt][1]};
            float2 v1 = {acc[mt][nt][2], acc[mt][nt][3]};
            *(float2*)(C + (size_t)r0 * ldc + c0)       = v0;
            *(float2*)(C + (size_t)(r0 + 8) * ldc + c0) = v1;
        }
    }
}

// ---------------- kernel 1: fused QKV projection ---------------------------
__global__ __launch_bounds__(256) void k_gemm_qkv()
{
    int cb = blockIdx.x;
    const unsigned* B;
    if (cb < 32)      B = g_W + WQ_OFF + (size_t)cb * DDIM * HD;
    else if (cb < 40) B = g_W + WK_OFF + (size_t)(cb - 32) * DDIM * HD;
    else              B = g_W + WV_OFF + (size_t)(cb - 40) * DDIM * HD;
    gemm_mma128_tf(g_Xt, DDIM, B, HD, g_QKV + (size_t)cb * HD, QKVC,
                   DDIM, blockIdx.y * 128);
}

// ---------------- kernel 2: RoPE + layout split + cache writeback ----------
__global__ __launch_bounds__(256) void k_rope(
    const int* __restrict__ positions,
    const int* __restrict__ widx,
    float* __restrict__ out_kc,
    float* __restrict__ out_vc)
{
    const int t = blockIdx.x;
    __shared__ float cs[64], sn[64];
    const int pos = positions[t];
    if (threadIdx.x < 64) {
        int i = threadIdx.x;
        double e = -((double)(2 * i) / 128.0);
        float inv = (float)pow(500000.0, e);
        float ang = (float)pos * inv;
        float s, c;
        sincosf(ang, &s, &c);
        cs[i] = c;
        sn[i] = s;
    }
    __syncthreads();

    const float* row = g_QKV + (size_t)t * QKVC;
    const int wi = widx[t];
    const float qscale = 0.08838834764831845f;  // 128^-0.5

    for (int idx = threadIdx.x; idx < NQ * 64; idx += blockDim.x) {
        int n = idx >> 6, i = idx & 63;
        float x1 = row[n * HD + i];
        float x2 = row[n * HD + 64 + i];
        float c = cs[i], s = sn[i];
        float* qd = g_Q + ((size_t)n * TSEQ + t) * HD;
        qd[i]      = (x1 * c - x2 * s) * qscale;
        qd[64 + i] = (x2 * c + x1 * s) * qscale;
    }
    for (int idx = threadIdx.x; idx < NKV * 64; idx += blockDim.x) {
        int kh = idx >> 6, i = idx & 63;
        float x1 = row[NQ * HD + kh * HD + i];
        float x2 = row[NQ * HD + kh * HD + 64 + i];
        float c = cs[i], s = sn[i];
        float o1 = x1 * c - x2 * s;
        float o2 = x2 * c + x1 * s;
        float* kd = g_K + ((size_t)kh * TSEQ + t) * HD;
        kd[i] = o1; kd[64 + i] = o2;
        float* kc = out_kc + ((size_t)wi * NKV + kh) * HD;
        kc[i] = o1; kc[64 + i] = o2;
    }
    for (int idx = threadIdx.x; idx < NKV * HD; idx += blockDim.x) {
        int kh = idx >> 7, h = idx & 127;
        float v = row[(NQ + NKV) * HD + kh * HD + h];
        g_V[((size_t)kh * TSEQ + t) * HD + h] = v;
        out_vc[((size_t)wi * NKV + kh) * HD + h] = v;
    }
}

// ---------------- kernel 3: tf32-mma causal flash attention ----------------
#define ATTN2_SMEM_FLOATS (8448 * 3 + 64)
__global__ __launch_bounds__(128) void k_attn_mma(const int* __restrict__ positions)
{
    extern __shared__ float sm[];
    float*    Qs  = sm;
    unsigned* Ks  = (unsigned*)(sm + 8448);
    unsigned* Vs  = (unsigned*)(sm + 16896);
    int*      PKs = (int*)(sm + 25344);
    unsigned* Ps  = Ks;               // alias (Ks dead once S is computed)

    const int n    = blockIdx.y;
    const int kh   = n >> 2;
    const int t0   = blockIdx.x * 64;
    const int tid  = threadIdx.x;
    const int lane = tid & 31;
    const int w    = tid >> 5;
    const int g    = lane >> 2;
    const int t    = lane & 3;

    const float* Qg = g_Q + ((size_t)n * TSEQ + t0) * HD;
    for (int i = tid; i < 2048; i += 128) {
        int r = i >> 5, c = (i & 31) << 2;
        *(float4*)(Qs + r * 132 + c) = *(const float4*)(Qg + (size_t)r * HD + c);
    }

    const int row0 = w * 16 + g;
    const int pq0 = positions[t0 + row0];
    const int pq1 = positions[t0 + row0 + 8];

    float m0 = -1e30f, m1 = -1e30f, l0 = 0.f, l1 = 0.f;
    float o[16][4];
#pragma unroll
    for (int nt = 0; nt < 16; nt++)
#pragma unroll
        for (int i = 0; i < 4; i++) o[nt][i] = 0.f;

    const float* Kg = g_K + (size_t)kh * TSEQ * HD;
    const float* Vg = g_V + (size_t)kh * TSEQ * HD;

    const int nchunks = blockIdx.x + 1;
    for (int ch = 0; ch < nchunks; ch++) {
        const int s0 = ch * 64;
        __syncthreads();

        for (int i = tid; i < 2048; i += 128) {
            int r = i >> 5, c = (i & 31) << 2;
            float4 kv = *(const float4*)(Kg + (size_t)(s0 + r) * HD + c);
            uint4 kb = {f2tf(kv.x), f2tf(kv.y), f2tf(kv.z), f2tf(kv.w)};
            *(uint4*)(Ks + r * 132 + c) = kb;
            float4 vv = *(const float4*)(Vg + (size_t)(s0 + r) * HD + c);
            uint4 vb = {f2tf(vv.x), f2tf(vv.y), f2tf(vv.z), f2tf(vv.w)};
            *(uint4*)(Vs + r * 132 + c) = vb;
        }
        if (tid < 64) PKs[tid] = positions[s0 + tid];
        __syncthreads();

        // ---- S = Q K^T, split-Q compensated ----
        float s[8][4];
#pragma unroll
        for (int nt = 0; nt < 8; nt++)
#pragma unroll
            for (int i = 0; i < 4; i++) s[nt][i] = 0.f;

#pragma unroll
        for (int ks = 0; ks < 16; ks++) {
            const int k0 = ks * 8;
            const float* qp = Qs + row0 * 132 + k0;
            float f0 = qp[t], f1 = qp[8 * 132 + t];
            float f2 = qp[t + 4], f3 = qp[8 * 132 + t + 4];
            unsigned ah[4], al[4];
            ah[0] = f2tf(f0); al[0] = f2tf(f0 - __uint_as_float(ah[0]));
            ah[1] = f2tf(f1); al[1] = f2tf(f1 - __uint_as_float(ah[1]));
            ah[2] = f2tf(f2); al[2] = f2tf(f2 - __uint_as_float(ah[2]));
            ah[3] = f2tf(f3); al[3] = f2tf(f3 - __uint_as_float(ah[3]));
#pragma unroll
            for (int nt = 0; nt < 8; nt++) {
                const unsigned* kp = Ks + (nt * 8 + g) * 132 + k0;
                unsigned bb[2] = {kp[t], kp[t + 4]};
                mma_tf32(s[nt], ah, bb);
                mma_tf32(s[nt], al, bb);
            }
        }

        // ---- mask + online softmax ----
        float mx0 = -1e30f, mx1 = -1e30f;
#pragma unroll
        for (int nt = 0; nt < 8; nt++) {
            const int col = nt * 8 + 2 * t;
            int2 pk = *(const int2*)(PKs + col);
            if (pq0 < pk.x) s[nt][0] = -1e30f;
            if (pq0 < pk.y) s[nt][1] = -1e30f;
            if (pq1 < pk.x) s[nt][2] = -1e30f;
            if (pq1 < pk.y) s[nt][3] = -1e30f;
            mx0 = fmaxf(mx0, fmaxf(s[nt][0], s[nt][1]));
            mx1 = fmaxf(mx1, fmaxf(s[nt][2], s[nt][3]));
        }
        mx0 = fmaxf(mx0, __shfl_xor_sync(0xffffffffu, mx0, 1));
        mx0 = fmaxf(mx0, __shfl_xor_sync(0xffffffffu, mx0, 2));
        mx1 = fmaxf(mx1, __shfl_xor_sync(0xffffffffu, mx1, 1));
        mx1 = fmaxf(mx1, __shfl_xor_sync(0xffffffffu, mx1, 2));

        const float mn0 = fmaxf(m0, mx0), mn1 = fmaxf(m1, mx1);
        const float c0 = __expf(m0 - mn0), c1 = __expf(m1 - mn1);
        m0 = mn0; m1 = mn1;

        float sum0 = 0.f, sum1 = 0.f;
#pragma unroll
        for (int nt = 0; nt < 8; nt++) {
            s[nt][0] = __expf(s[nt][0] - mn0);
            s[nt][1] = __expf(s[nt][1] - mn0);
            s[nt][2] = __expf(s[nt][2] - mn1);
            s[nt][3] = __expf(s[nt][3] - mn1);
            sum0 += s[nt][0] + s[nt][1];
            sum1 += s[nt][2] + s[nt][3];
        }
        sum0 += __shfl_xor_sync(0xffffffffu, sum0, 1);
        sum0 += __shfl_xor_sync(0xffffffffu, sum0, 2);
        sum1 += __shfl_xor_sync(0xffffffffu, sum1, 1);
        sum1 += __shfl_xor_sync(0xffffffffu, sum1, 2);
        l0 = l0 * c0 + sum0;
        l1 = l1 * c1 + sum1;

#pragma unroll
        for (int nt = 0; nt < 16; nt++) {
            o[nt][0] *= c0; o[nt][1] *= c0;
            o[nt][2] *= c1; o[nt][3] *= c1;
        }

        __syncthreads();

#pragma unroll
        for (int nt = 0; nt < 8; nt++) {
            const int col = nt * 8 + 2 * t;
            uint2 p01 = {f2tf(s[nt][0]), f2tf(s[nt][1])};
            uint2 p23 = {f2tf(s[nt][2]), f2tf(s[nt][3])};
            *(uint2*)(Ps + row0 * 68 + col)       = p01;
            *(uint2*)(Ps + (row0 + 8) * 68 + col) = p23;
        }
        __syncwarp();

#pragma unroll
        for (int ks = 0; ks < 8; ks++) {
            const int k0 = ks * 8;
            const unsigned* pp = Ps + row0 * 68 + k0;
            unsigned a[4] = {pp[t], pp[8 * 68 + t], pp[t + 4], pp[8 * 68 + t + 4]};
#pragma unroll
            for (int nt = 0; nt < 16; nt++) {
                const unsigned* vp = Vs + (k0 + t) * 132 + nt * 8 + g;
                unsigned bb[2] = {vp[0], vp[4 * 132]};
                mma_tf32(o[nt], a, bb);
            }
        }
    }

    // ---- epilogue: write tf32 bits (feeds k_gemm_o directly) ----
    const float inv0 = 1.f / l0, inv1 = 1.f / l1;
    unsigned* outr0 = g_A2 + (size_t)(t0 + row0) * DDIM + n * HD;
    unsigned* outr1 = g_A2 + (size_t)(t0 + row0 + 8) * DDIM + n * HD;
#pragma unroll
    for (int nt = 0; nt < 16; nt++) {
        const int col = nt * 8 + 2 * t;
        uint2 v0 = {f2tf(o[nt][0] * inv0), f2tf(o[nt][1] * inv0)};
        uint2 v1 = {f2tf(o[nt][2] * inv1), f2tf(o[nt][3] * inv1)};
        *(uint2*)(outr0 + col) = v0;
        *(uint2*)(outr1 + col) = v1;
    }
}

// ---------------- kernel 4: output projection ------------------------------
__global__ __launch_bounds__(256) void k_gemm_o(float* __restrict__ out_o)
{
    gemm_mma128_tf(g_A2, DDIM, g_W + WO_OFF + (size_t)blockIdx.x * 128, DDIM,
                   out_o + (size_t)blockIdx.x * 128, DDIM,
                   DDIM, blockIdx.y * 128);
}

// ---------------- launch ----------------------------------------------------
extern "C" void kernel_launch(void* const* d_in, const int* in_sizes, int n_in,
                              void* d_out, int out_size)
{
    (void)in_sizes; (void)n_in; (void)out_size;
    const float* x     = (const float*)d_in[0];
    const float* wq    = (const float*)d_in[1];
    const float* wk    = (const float*)d_in[2];
    const float* wv    = (const float*)d_in[3];
    const float* wo    = (const float*)d_in[4];
    const float* kc_in = (const float*)d_in[5];
    const float* vc_in = (const float*)d_in[6];
    const int* positions = (const int*)d_in[7];
    const int* widx      = (const int*)d_in[8];

    float* out_kc = (float*)d_out;
    float* out_vc = out_kc + (size_t)NSLOTS * NKV * HD;
    float* out_o  = out_vc + (size_t)NSLOTS * NKV * HD;

    const size_t cacheBytes = (size_t)NSLOTS * NKV * HD * sizeof(float);
    cudaMemcpyAsync(out_kc, kc_in, cacheBytes, cudaMemcpyDeviceToDevice, 0);
    cudaMemcpyAsync(out_vc, vc_in, cacheBytes, cudaMemcpyDeviceToDevice, 0);

    // ---- prep: convert weights + x to tf32 bit format ----
    unsigned* gW;  cudaGetSymbolAddress((void**)&gW,  g_W);
    unsigned* gXt; cudaGetSymbolAddress((void**)&gXt, g_Xt);
    {
        int n4;
        n4 = (int)(WQ_ELEMS / 4);
        k_cvt_tf32<<<(n4 + 255) / 256, 256>>>((const float4*)wq, (uint4*)(gW + WQ_OFF), n4);
        n4 = (int)(WK_ELEMS / 4);
        k_cvt_tf32<<<(n4 + 255) / 256, 256>>>((const float4*)wk, (uint4*)(gW + WK_OFF), n4);
        k_cvt_tf32<<<(n4 + 255) / 256, 256>>>((const float4*)wv, (uint4*)(gW + WV_OFF), n4);
        n4 = (int)(WO_ELEMS / 4);
        k_cvt_tf32<<<(n4 + 255) / 256, 256>>>((const float4*)wo, (uint4*)(gW + WO_OFF), n4);
        n4 = (int)((size_t)TSEQ * DDIM / 4);
        k_cvt_tf32<<<(n4 + 255) / 256, 256>>>((const float4*)x, (uint4*)gXt, n4);
    }

    k_gemm_qkv<<<dim3(48, TSEQ / 128), 256, 0, 0>>>();
    k_rope<<<TSEQ, 256, 0, 0>>>(positions, widx, out_kc, out_vc);

    const int attn_smem = ATTN2_SMEM_FLOATS * (int)sizeof(float);
    cudaFuncSetAttribute(k_attn_mma,
                         cudaFuncAttributeMaxDynamicSharedMemorySize, attn_smem);
    k_attn_mma<<<dim3(TSEQ / 64, NQ), 128, attn_smem, 0>>>(positions);

    k_gemm_o<<<dim3(DDIM / 128, TSEQ / 128), 256, 0, 0>>>(out_o);
}

// round 6
// speedup vs baseline: 1.0011x; 1.0011x over previous
#include <cuda_runtime.h>
#include <cstdint>
#include <stdint.h>
#include <math.h>

// Problem constants (fixed by the dataset)
#define TSEQ   2048
#define DDIM   4096
#define NQ     32
#define NKV    8
#define HD     128
#define NSLOTS 32768
#define QKVC   6144   // 32*128 + 8*128 + 8*128

// ---------------- scratch (static device allocations; no cudaMalloc) -------
__device__ float    g_QKV[(size_t)TSEQ * QKVC];      // [t][6144]
__device__ float    g_Q  [(size_t)NQ  * TSEQ * HD];  // [n][t][h]
__device__ float    g_K  [(size_t)NKV * TSEQ * HD];  // [kh][t][h]
__device__ float    g_V  [(size_t)NKV * TSEQ * HD];  // [kh][t][h]
__device__ unsigned g_A2 [(size_t)TSEQ * DDIM];      // [t][n*128+h] tf32 bits
__device__ unsigned g_Xt [(size_t)TSEQ * DDIM];      // x tf32 bits

// ---------------- tf32 mma helpers -----------------------------------------
__device__ __forceinline__ unsigned f2tf(float x) {
    unsigned r;
    asm("cvt.rna.tf32.f32 %0, %1;" : "=r"(r) : "f"(x));
    return r;
}

__device__ __forceinline__ void mma_tf32(float* d, const unsigned* a,
                                         const unsigned* b) {
    asm volatile(
        "mma.sync.aligned.m16n8k8.row.col.f32.tf32.tf32.f32 "
        "{%0,%1,%2,%3}, {%4,%5,%6,%7}, {%8,%9}, {%0,%1,%2,%3};"
        : "+f"(d[0]), "+f"(d[1]), "+f"(d[2]), "+f"(d[3])
        : "r"(a[0]), "r"(a[1]), "r"(a[2]), "r"(a[3]), "r"(b[0]), "r"(b[1]));
}

__device__ __forceinline__ void cp16(unsigned smem, const void* g) {
    asm volatile("cp.async.cg.shared.global [%0], [%1], 16;\n"
                 :: "r"(smem), "l"(g));
}

// ---------------- prep: fp32 -> tf32 bits (elementwise, x only) ------------
__global__ __launch_bounds__(256) void k_cvt_tf32(
    const float4* __restrict__ in, uint4* __restrict__ out, int n4)
{
    int i = blockIdx.x * 256 + threadIdx.x;
    if (i < n4) {
        float4 v = in[i];
        uint4 o = {f2tf(v.x), f2tf(v.y), f2tf(v.z), f2tf(v.w)};
        out[i] = o;
    }
}

// ---------------- 128x128 tf32 GEMM, 4-stage cp.async pipeline -------------
// A: row-major tf32 BITS [.., lda]; B: row-major FP32 [Kdim, ldb] (converted
// at fragment load). 256 threads (8 warps 2x4). Kdim % 16 == 0.
#define NSTG 4
__device__ __forceinline__ void gemm_mma128_hyb(
    const unsigned* __restrict__ A, int lda,
    const float* __restrict__ B, int ldb,
    float* __restrict__ C, int ldc,
    int Kdim, int rowBase)
{
    __shared__ unsigned As[NSTG][128][20];   // pad 20
    __shared__ float    Bs[NSTG][16][136];   // pad 136

    const int tid  = threadIdx.x;
    const int lane = tid & 31;
    const int warp = tid >> 5;
    const int wM   = warp >> 2;
    const int wN   = warp & 3;
    const int g    = lane >> 2;
    const int t    = lane & 3;

    const int ar = tid >> 2, ac = (tid & 3) << 2;
    const int br = tid >> 5, bc = (tid & 31) << 2;

    const unsigned* Ab = A + (size_t)rowBase * lda;

    float acc[4][4][4];
#pragma unroll
    for (int mt = 0; mt < 4; mt++)
#pragma unroll
        for (int nt = 0; nt < 4; nt++)
#pragma unroll
            for (int i = 0; i < 4; i++) acc[mt][nt][i] = 0.f;

    const unsigned sA0 = (unsigned)__cvta_generic_to_shared(&As[0][0][0]);
    const unsigned sB0 = (unsigned)__cvta_generic_to_shared(&Bs[0][0][0]);
    const unsigned stASz = (unsigned)(128 * 20 * 4);
    const unsigned stBSz = (unsigned)(16 * 136 * 4);

    const int niter = Kdim >> 4;

    // ---- prologue: stages 0..2, one commit group each ----
#pragma unroll
    for (int p = 0; p < NSTG - 1; p++) {
        if (p < niter) {
            const int k0 = p << 4;
            const unsigned stA = sA0 + (unsigned)p * stASz;
            const unsigned stB = sB0 + (unsigned)p * stBSz;
            cp16(stA + (unsigned)((ar)      * 20 + ac) * 4u, Ab + (size_t)ar * lda + k0 + ac);
            cp16(stA + (unsigned)((ar + 64) * 20 + ac) * 4u, Ab + (size_t)(ar + 64) * lda + k0 + ac);
            cp16(stB + (unsigned)((br)      * 136 + bc) * 4u, B + (size_t)(k0 + br) * ldb + bc);
            cp16(stB + (unsigned)((br + 8)  * 136 + bc) * 4u, B + (size_t)(k0 + br + 8) * ldb + bc);
        }
        asm volatile("cp.async.commit_group;");
    }

    for (int it = 0; it < niter; it++) {
        // prefetch stage it+3
        if (it + NSTG - 1 < niter) {
            const int k0 = (it + NSTG - 1) << 4;
            const int bsel = (it + NSTG - 1) & (NSTG - 1);
            const unsigned stA = sA0 + (unsigned)bsel * stASz;
            const unsigned stB = sB0 + (unsigned)bsel * stBSz;
            cp16(stA + (unsigned)((ar)      * 20 + ac) * 4u, Ab + (size_t)ar * lda + k0 + ac);
            cp16(stA + (unsigned)((ar + 64) * 20 + ac) * 4u, Ab + (size_t)(ar + 64) * lda + k0 + ac);
            cp16(stB + (unsigned)((br)      * 136 + bc) * 4u, B + (size_t)(k0 + br) * ldb + bc);
            cp16(stB + (unsigned)((br + 8)  * 136 + bc) * 4u, B + (size_t)(k0 + br + 8) * ldb + bc);
        }
        asm volatile("cp.async.commit_group;");
        asm volatile("cp.async.wait_group %0;" :: "n"(NSTG - 1));
        __syncthreads();

        const int st = it & (NSTG - 1);
#pragma unroll
        for (int ks = 0; ks < 2; ks++) {
            unsigned af[4][4], bf[4][2];
#pragma unroll
            for (int mt = 0; mt < 4; mt++) {
                const unsigned* p = &As[st][wM * 64 + mt * 16 + g][ks * 8 + t];
                af[mt][0] = p[0];
                af[mt][1] = p[8 * 20];
                af[mt][2] = p[4];
                af[mt][3] = p[8 * 20 + 4];
            }
#pragma unroll
            for (int nt = 0; nt < 4; nt++) {
                bf[nt][0] = f2tf(Bs[st][ks * 8 + t    ][wN * 32 + nt * 8 + g]);
                bf[nt][1] = f2tf(Bs[st][ks * 8 + t + 4][wN * 32 + nt * 8 + g]);
            }
#pragma unroll
            for (int mt = 0; mt < 4; mt++)
#pragma unroll
                for (int nt = 0; nt < 4; nt++)
                    mma_tf32(acc[mt][nt], af[mt], bf[nt]);
        }
        __syncthreads();
    }

#pragma unroll
    for (int mt = 0; mt < 4; mt++) {
#pragma unroll
        for (int nt = 0; nt < 4; nt++) {
            const int r0 = rowBase + wM * 64 + mt * 16 + g;
            const int c0 = wN * 32 + nt * 8 + 2 * t;
            float2 v0 = {acc[mt][nt][0], acc[mt][nt][1]};
            float2 v1 = {acc[mt][nt][2], acc[mt][nt][3]};
            *(float2*)(C + (size_t)r0 * ldc + c0)       = v0;
            *(float2*)(C + (size_t)(r0 + 8) * ldc + c0) = v1;
        }
    }
}

// ---------------- kernel 1: fused QKV projection ---------------------------
__global__ __launch_bounds__(256) void k_gemm_qkv(
    const float* __restrict__ wq,
    const float* __restrict__ wk,
    const float* __restrict__ wv)
{
    int cb = blockIdx.x;
    const float* B;
    if (cb < 32)      B = wq + (size_t)cb * DDIM * HD;
    else if (cb < 40) B = wk + (size_t)(cb - 32) * DDIM * HD;
    else              B = wv + (size_t)(cb - 40) * DDIM * HD;
    gemm_mma128_hyb(g_Xt, DDIM, B, HD, g_QKV + (size_t)cb * HD, QKVC,
                    DDIM, blockIdx.y * 128);
}

// ---------------- kernel 2: RoPE + layout split + cache writeback ----------
__global__ __launch_bounds__(256) void k_rope(
    const int* __restrict__ positions,
    const int* __restrict__ widx,
    float* __restrict__ out_kc,
    float* __restrict__ out_vc)
{
    const int t = blockIdx.x;
    __shared__ float cs[64], sn[64];
    const int pos = positions[t];
    if (threadIdx.x < 64) {
        int i = threadIdx.x;
        double e = -((double)(2 * i) / 128.0);
        float inv = (float)pow(500000.0, e);
        float ang = (float)pos * inv;
        float s, c;
        sincosf(ang, &s, &c);
        cs[i] = c;
        sn[i] = s;
    }
    __syncthreads();

    const float* row = g_QKV + (size_t)t * QKVC;
    const int wi = widx[t];
    const float qscale = 0.08838834764831845f;  // 128^-0.5

    for (int idx = threadIdx.x; idx < NQ * 64; idx += blockDim.x) {
        int n = idx >> 6, i = idx & 63;
        float x1 = row[n * HD + i];
        float x2 = row[n * HD + 64 + i];
        float c = cs[i], s = sn[i];
        float* qd = g_Q + ((size_t)n * TSEQ + t) * HD;
        qd[i]      = (x1 * c - x2 * s) * qscale;
        qd[64 + i] = (x2 * c + x1 * s) * qscale;
    }
    for (int idx = threadIdx.x; idx < NKV * 64; idx += blockDim.x) {
        int kh = idx >> 6, i = idx & 63;
        float x1 = row[NQ * HD + kh * HD + i];
        float x2 = row[NQ * HD + kh * HD + 64 + i];
        float c = cs[i], s = sn[i];
        float o1 = x1 * c - x2 * s;
        float o2 = x2 * c + x1 * s;
        float* kd = g_K + ((size_t)kh * TSEQ + t) * HD;
        kd[i] = o1; kd[64 + i] = o2;
        float* kc = out_kc + ((size_t)wi * NKV + kh) * HD;
        kc[i] = o1; kc[64 + i] = o2;
    }
    for (int idx = threadIdx.x; idx < NKV * HD; idx += blockDim.x) {
        int kh = idx >> 7, h = idx & 127;
        float v = row[(NQ + NKV) * HD + kh * HD + h];
        g_V[((size_t)kh * TSEQ + t) * HD + h] = v;
        out_vc[((size_t)wi * NKV + kh) * HD + h] = v;
    }
}

// ---------------- kernel 3: tf32-mma causal flash attention ----------------
#define ATTN2_SMEM_FLOATS (8448 * 3 + 64)
__global__ __launch_bounds__(128) void k_attn_mma(const int* __restrict__ positions)
{
    extern __shared__ float sm[];
    float*    Qs  = sm;
    unsigned* Ks  = (unsigned*)(sm + 8448);
    unsigned* Vs  = (unsigned*)(sm + 16896);
    int*      PKs = (int*)(sm + 25344);
    unsigned* Ps  = Ks;               // alias (Ks dead once S is computed)

    const int n    = blockIdx.y;
    const int kh   = n >> 2;
    const int t0   = blockIdx.x * 64;
    const int tid  = threadIdx.x;
    const int lane = tid & 31;
    const int w    = tid >> 5;
    const int g    = lane >> 2;
    const int t    = lane & 3;

    const float* Qg = g_Q + ((size_t)n * TSEQ + t0) * HD;
    for (int i = tid; i < 2048; i += 128) {
        int r = i >> 5, c = (i & 31) << 2;
        *(float4*)(Qs + r * 132 + c) = *(const float4*)(Qg + (size_t)r * HD + c);
    }

    const int row0 = w * 16 + g;
    const int pq0 = positions[t0 + row0];
    const int pq1 = positions[t0 + row0 + 8];

    float m0 = -1e30f, m1 = -1e30f, l0 = 0.f, l1 = 0.f;
    float o[16][4];
#pragma unroll
    for (int nt = 0; nt < 16; nt++)
#pragma unroll
        for (int i = 0; i < 4; i++) o[nt][i] = 0.f;

    const float* Kg = g_K + (size_t)kh * TSEQ * HD;
    const float* Vg = g_V + (size_t)kh * TSEQ * HD;

    const int nchunks = blockIdx.x + 1;
    for (int ch = 0; ch < nchunks; ch++) {
        const int s0 = ch * 64;
        __syncthreads();

        for (int i = tid; i < 2048; i += 128) {
            int r = i >> 5, c = (i & 31) << 2;
            float4 kv = *(const float4*)(Kg + (size_t)(s0 + r) * HD + c);
            uint4 kb = {f2tf(kv.x), f2tf(kv.y), f2tf(kv.z), f2tf(kv.w)};
            *(uint4*)(Ks + r * 132 + c) = kb;
            float4 vv = *(const float4*)(Vg + (size_t)(s0 + r) * HD + c);
            uint4 vb = {f2tf(vv.x), f2tf(vv.y), f2tf(vv.z), f2tf(vv.w)};
            *(uint4*)(Vs + r * 132 + c) = vb;
        }
        if (tid < 64) PKs[tid] = positions[s0 + tid];
        __syncthreads();

        // ---- S = Q K^T, split-Q compensated ----
        float s[8][4];
#pragma unroll
        for (int nt = 0; nt < 8; nt++)
#pragma unroll
            for (int i = 0; i < 4; i++) s[nt][i] = 0.f;

#pragma unroll
        for (int ks = 0; ks < 16; ks++) {
            const int k0 = ks * 8;
            const float* qp = Qs + row0 * 132 + k0;
            float f0 = qp[t], f1 = qp[8 * 132 + t];
            float f2 = qp[t + 4], f3 = qp[8 * 132 + t + 4];
            unsigned ah[4], al[4];
            ah[0] = f2tf(f0); al[0] = f2tf(f0 - __uint_as_float(ah[0]));
            ah[1] = f2tf(f1); al[1] = f2tf(f1 - __uint_as_float(ah[1]));
            ah[2] = f2tf(f2); al[2] = f2tf(f2 - __uint_as_float(ah[2]));
            ah[3] = f2tf(f3); al[3] = f2tf(f3 - __uint_as_float(ah[3]));
#pragma unroll
            for (int nt = 0; nt < 8; nt++) {
                const unsigned* kp = Ks + (nt * 8 + g) * 132 + k0;
                unsigned bb[2] = {kp[t], kp[t + 4]};
                mma_tf32(s[nt], ah, bb);
                mma_tf32(s[nt], al, bb);
            }
        }

        // ---- mask + online softmax ----
        float mx0 = -1e30f, mx1 = -1e30f;
#pragma unroll
        for (int nt = 0; nt < 8; nt++) {
            const int col = nt * 8 + 2 * t;
            int2 pk = *(const int2*)(PKs + col);
            if (pq0 < pk.x) s[nt][0] = -1e30f;
            if (pq0 < pk.y) s[nt][1] = -1e30f;
            if (pq1 < pk.x) s[nt][2] = -1e30f;
            if (pq1 < pk.y) s[nt][3] = -1e30f;
            mx0 = fmaxf(mx0, fmaxf(s[nt][0], s[nt][1]));
            mx1 = fmaxf(mx1, fmaxf(s[nt][2], s[nt][3]));
        }
        mx0 = fmaxf(mx0, __shfl_xor_sync(0xffffffffu, mx0, 1));
        mx0 = fmaxf(mx0, __shfl_xor_sync(0xffffffffu, mx0, 2));
        mx1 = fmaxf(mx1, __shfl_xor_sync(0xffffffffu, mx1, 1));
        mx1 = fmaxf(mx1, __shfl_xor_sync(0xffffffffu, mx1, 2));

        const float mn0 = fmaxf(m0, mx0), mn1 = fmaxf(m1, mx1);
        const float c0 = __expf(m0 - mn0), c1 = __expf(m1 - mn1);
        m0 = mn0; m1 = mn1;

        float sum0 = 0.f, sum1 = 0.f;
#pragma unroll
        for (int nt = 0; nt < 8; nt++) {
            s[nt][0] = __expf(s[nt][0] - mn0);
            s[nt][1] = __expf(s[nt][1] - mn0);
            s[nt][2] = __expf(s[nt][2] - mn1);
            s[nt][3] = __expf(s[nt][3] - mn1);
            sum0 += s[nt][0] + s[nt][1];
            sum1 += s[nt][2] + s[nt][3];
        }
        sum0 += __shfl_xor_sync(0xffffffffu, sum0, 1);
        sum0 += __shfl_xor_sync(0xffffffffu, sum0, 2);
        sum1 += __shfl_xor_sync(0xffffffffu, sum1, 1);
        sum1 += __shfl_xor_sync(0xffffffffu, sum1, 2);
        l0 = l0 * c0 + sum0;
        l1 = l1 * c1 + sum1;

#pragma unroll
        for (int nt = 0; nt < 16; nt++) {
            o[nt][0] *= c0; o[nt][1] *= c0;
            o[nt][2] *= c1; o[nt][3] *= c1;
        }

        __syncthreads();

#pragma unroll
        for (int nt = 0; nt < 8; nt++) {
            const int col = nt * 8 + 2 * t;
            uint2 p01 = {f2tf(s[nt][0]), f2tf(s[nt][1])};
            uint2 p23 = {f2tf(s[nt][2]), f2tf(s[nt][3])};
            *(uint2*)(Ps + row0 * 68 + col)       = p01;
            *(uint2*)(Ps + (row0 + 8) * 68 + col) = p23;
        }
        __syncwarp();

#pragma unroll
        for (int ks = 0; ks < 8; ks++) {
            const int k0 = ks * 8;
            const unsigned* pp = Ps + row0 * 68 + k0;
            unsigned a[4] = {pp[t], pp[8 * 68 + t], pp[t + 4], pp[8 * 68 + t + 4]};
#pragma unroll
            for (int nt = 0; nt < 16; nt++) {
                const unsigned* vp = Vs + (k0 + t) * 132 + nt * 8 + g;
                unsigned bb[2] = {vp[0], vp[4 * 132]};
                mma_tf32(o[nt], a, bb);
            }
        }
    }

    // ---- epilogue: write tf32 bits (feeds k_gemm_o directly) ----
    const float inv0 = 1.f / l0, inv1 = 1.f / l1;
    unsigned* outr0 = g_A2 + (size_t)(t0 + row0) * DDIM + n * HD;
    unsigned* outr1 = g_A2 + (size_t)(t0 + row0 + 8) * DDIM + n * HD;
#pragma unroll
    for (int nt = 0; nt < 16; nt++) {
        const int col = nt * 8 + 2 * t;
        uint2 v0 = {f2tf(o[nt][0] * inv0), f2tf(o[nt][1] * inv0)};
        uint2 v1 = {f2tf(o[nt][2] * inv1), f2tf(o[nt][3] * inv1)};
        *(uint2*)(outr0 + col) = v0;
        *(uint2*)(outr1 + col) = v1;
    }
}

// ---------------- kernel 4: output projection ------------------------------
__global__ __launch_bounds__(256) void k_gemm_o(
    const float* __restrict__ wo, float* __restrict__ out_o)
{
    gemm_mma128_hyb(g_A2, DDIM, wo + (size_t)blockIdx.x * 128, DDIM,
                    out_o + (size_t)blockIdx.x * 128, DDIM,
                    DDIM, blockIdx.y * 128);
}

// ---------------- launch ----------------------------------------------------
extern "C" void kernel_launch(void* const* d_in, const int* in_sizes, int n_in,
                              void* d_out, int out_size)
{
    (void)in_sizes; (void)n_in; (void)out_size;
    const float* x     = (const float*)d_in[0];
    const float* wq    = (const float*)d_in[1];
    const float* wk    = (const float*)d_in[2];
    const float* wv    = (const float*)d_in[3];
    const float* wo    = (const float*)d_in[4];
    const float* kc_in = (const float*)d_in[5];
    const float* vc_in = (const float*)d_in[6];
    const int* positions = (const int*)d_in[7];
    const int* widx      = (const int*)d_in[8];

    float* out_kc = (float*)d_out;
    float* out_vc = out_kc + (size_t)NSLOTS * NKV * HD;
    float* out_o  = out_vc + (size_t)NSLOTS * NKV * HD;

    const size_t cacheBytes = (size_t)NSLOTS * NKV * HD * sizeof(float);
    cudaMemcpyAsync(out_kc, kc_in, cacheBytes, cudaMemcpyDeviceToDevice, 0);
    cudaMemcpyAsync(out_vc, vc_in, cacheBytes, cudaMemcpyDeviceToDevice, 0);

    // ---- prep: convert x to tf32 bit format (cheap, 33MB) ----
    unsigned* gXt; cudaGetSymbolAddress((void**)&gXt, g_Xt);
    {
        int n4 = (int)((size_t)TSEQ * DDIM / 4);
        k_cvt_tf32<<<(n4 + 255) / 256, 256>>>((const float4*)x, (uint4*)gXt, n4);
    }

    k_gemm_qkv<<<dim3(48, TSEQ / 128), 256, 0, 0>>>(wq, wk, wv);
    k_rope<<<TSEQ, 256, 0, 0>>>(positions, widx, out_kc, out_vc);

    const int attn_smem = ATTN2_SMEM_FLOATS * (int)sizeof(float);
    cudaFuncSetAttribute(k_attn_mma,
                         cudaFuncAttributeMaxDynamicSharedMemorySize, attn_smem);
    k_attn_mma<<<dim3(TSEQ / 64, NQ), 128, attn_smem, 0>>>(positions);

    k_gemm_o<<<dim3(DDIM / 128, TSEQ / 128), 256, 0, 0>>>(wo, out_o);
}

// round 7
// speedup vs baseline: 1.0413x; 1.0402x over previous
#include <cuda_runtime.h>
#include <cstdint>
#include <stdint.h>
#include <math.h>

// Problem constants (fixed by the dataset)
#define TSEQ   2048
#define DDIM   4096
#define NQ     32
#define NKV    8
#define HD     128
#define NSLOTS 32768
#define QKVC   6144   // 32*128 + 8*128 + 8*128

// ---------------- scratch (static device allocations; no cudaMalloc) -------
__device__ float    g_QKV[(size_t)TSEQ * QKVC];      // [t][6144] fp32
__device__ unsigned g_Q  [(size_t)NQ  * TSEQ * HD];  // [n][t][h] tf32 bits (scaled)
__device__ unsigned g_K  [(size_t)NKV * TSEQ * HD];  // [kh][t][h] tf32 bits
__device__ unsigned g_V  [(size_t)NKV * TSEQ * HD];  // [kh][t][h] tf32 bits
__device__ unsigned g_A2 [(size_t)TSEQ * DDIM];      // [t][n*128+h] tf32 bits

// ---------------- tf32 mma helpers -----------------------------------------
__device__ __forceinline__ unsigned f2tf(float x) {
    unsigned r;
    asm("cvt.rna.tf32.f32 %0, %1;" : "=r"(r) : "f"(x));
    return r;
}

__device__ __forceinline__ void mma_tf32(float* d, const unsigned* a,
                                         const unsigned* b) {
    asm volatile(
        "mma.sync.aligned.m16n8k8.row.col.f32.tf32.tf32.f32 "
        "{%0,%1,%2,%3}, {%4,%5,%6,%7}, {%8,%9}, {%0,%1,%2,%3};"
        : "+f"(d[0]), "+f"(d[1]), "+f"(d[2]), "+f"(d[3])
        : "r"(a[0]), "r"(a[1]), "r"(a[2]), "r"(a[3]), "r"(b[0]), "r"(b[1]));
}

__device__ __forceinline__ void cp16(unsigned smem, const void* g) {
    asm volatile("cp.async.cg.shared.global [%0], [%1], 16;\n"
                 :: "r"(smem), "l"(g));
}

// ---------------- 128x128 tf32 GEMM, 3-stage single-sync pipeline ----------
// A: row-major [.., lda] — tf32 BITS if ABITS else FP32 (cvt at frag load).
// B: row-major FP32 [Kdim, ldb] (cvt at frag load).
// 256 threads (8 warps 2x4). Kdim % 16 == 0.
template <bool ABITS>
__device__ __forceinline__ void gemm_mma128_t(
    const void* __restrict__ Av, int lda,
    const float* __restrict__ B, int ldb,
    float* __restrict__ C, int ldc,
    int Kdim, int rowBase)
{
    __shared__ unsigned As[3][128][20];   // pad 20
    __shared__ float    Bs[3][16][136];   // pad 136

    const int tid  = threadIdx.x;
    const int lane = tid & 31;
    const int warp = tid >> 5;
    const int wM   = warp >> 2;
    const int wN   = warp & 3;
    const int g    = lane >> 2;
    const int t    = lane & 3;

    const int ar = tid >> 2, ac = (tid & 3) << 2;
    const int br = tid >> 5, bc = (tid & 31) << 2;

    const char* Ab = (const char*)Av + (size_t)rowBase * lda * 4;

    float acc[4][4][4];
#pragma unroll
    for (int mt = 0; mt < 4; mt++)
#pragma unroll
        for (int nt = 0; nt < 4; nt++)
#pragma unroll
            for (int i = 0; i < 4; i++) acc[mt][nt][i] = 0.f;

    const unsigned sA0 = (unsigned)__cvta_generic_to_shared(&As[0][0][0]);
    const unsigned sB0 = (unsigned)__cvta_generic_to_shared(&Bs[0][0][0]);
    const unsigned stASz = (unsigned)(128 * 20 * 4);
    const unsigned stBSz = (unsigned)(16 * 136 * 4);

    const int niter = Kdim >> 4;

    // ---- prologue: stages 0,1 ----
#pragma unroll
    for (int p = 0; p < 2; p++) {
        const int k0 = p << 4;
        const unsigned stA = sA0 + (unsigned)p * stASz;
        const unsigned stB = sB0 + (unsigned)p * stBSz;
        cp16(stA + (unsigned)((ar)      * 20 + ac) * 4u, Ab + ((size_t)ar * lda + k0 + ac) * 4);
        cp16(stA + (unsigned)((ar + 64) * 20 + ac) * 4u, Ab + ((size_t)(ar + 64) * lda + k0 + ac) * 4);
        cp16(stB + (unsigned)((br)      * 136 + bc) * 4u, B + (size_t)(k0 + br) * ldb + bc);
        cp16(stB + (unsigned)((br + 8)  * 136 + bc) * 4u, B + (size_t)(k0 + br + 8) * ldb + bc);
        asm volatile("cp.async.commit_group;");
    }

    for (int it = 0; it < niter; it++) {
        asm volatile("cp.async.wait_group 1;");
        __syncthreads();   // stage `it` ready; all threads done reading stage it-1

        // issue stage it+2 into buffer (it+2)%3 (safe: == (it-1)%3, drained by sync)
        if (it + 2 < niter) {
            const int k0 = (it + 2) << 4;
            const int bsel = (it + 2) % 3;
            const unsigned stA = sA0 + (unsigned)bsel * stASz;
            const unsigned stB = sB0 + (unsigned)bsel * stBSz;
            cp16(stA + (unsigned)((ar)      * 20 + ac) * 4u, Ab + ((size_t)ar * lda + k0 + ac) * 4);
            cp16(stA + (unsigned)((ar + 64) * 20 + ac) * 4u, Ab + ((size_t)(ar + 64) * lda + k0 + ac) * 4);
            cp16(stB + (unsigned)((br)      * 136 + bc) * 4u, B + (size_t)(k0 + br) * ldb + bc);
            cp16(stB + (unsigned)((br + 8)  * 136 + bc) * 4u, B + (size_t)(k0 + br + 8) * ldb + bc);
        }
        asm volatile("cp.async.commit_group;");

        const int st = it % 3;
#pragma unroll
        for (int ks = 0; ks < 2; ks++) {
            unsigned af[4][4], bf[4][2];
#pragma unroll
            for (int mt = 0; mt < 4; mt++) {
                const unsigned* p = &As[st][wM * 64 + mt * 16 + g][ks * 8 + t];
                if (ABITS) {
                    af[mt][0] = p[0];
                    af[mt][1] = p[8 * 20];
                    af[mt][2] = p[4];
                    af[mt][3] = p[8 * 20 + 4];
                } else {
                    af[mt][0] = f2tf(__uint_as_float(p[0]));
                    af[mt][1] = f2tf(__uint_as_float(p[8 * 20]));
                    af[mt][2] = f2tf(__uint_as_float(p[4]));
                    af[mt][3] = f2tf(__uint_as_float(p[8 * 20 + 4]));
                }
            }
#pragma unroll
            for (int nt = 0; nt < 4; nt++) {
                bf[nt][0] = f2tf(Bs[st][ks * 8 + t    ][wN * 32 + nt * 8 + g]);
                bf[nt][1] = f2tf(Bs[st][ks * 8 + t + 4][wN * 32 + nt * 8 + g]);
            }
#pragma unroll
            for (int mt = 0; mt < 4; mt++)
#pragma unroll
                for (int nt = 0; nt < 4; nt++)
                    mma_tf32(acc[mt][nt], af[mt], bf[nt]);
        }
    }

#pragma unroll
    for (int mt = 0; mt < 4; mt++) {
#pragma unroll
        for (int nt = 0; nt < 4; nt++) {
            const int r0 = rowBase + wM * 64 + mt * 16 + g;
            const int c0 = wN * 32 + nt * 8 + 2 * t;
            float2 v0 = {acc[mt][nt][0], acc[mt][nt][1]};
            float2 v1 = {acc[mt][nt][2], acc[mt][nt][3]};
            *(float2*)(C + (size_t)r0 * ldc + c0)       = v0;
            *(float2*)(C + (size_t)(r0 + 8) * ldc + c0) = v1;
        }
    }
}

// ---------------- kernel 1: fused QKV projection ---------------------------
__global__ __launch_bounds__(256) void k_gemm_qkv(
    const float* __restrict__ x,
    const float* __restrict__ wq,
    const float* __restrict__ wk,
    const float* __restrict__ wv)
{
    int cb = blockIdx.x;
    const float* B;
    if (cb < 32)      B = wq + (size_t)cb * DDIM * HD;
    else if (cb < 40) B = wk + (size_t)(cb - 32) * DDIM * HD;
    else              B = wv + (size_t)(cb - 40) * DDIM * HD;
    gemm_mma128_t<false>(x, DDIM, B, HD, g_QKV + (size_t)cb * HD, QKVC,
                         DDIM, blockIdx.y * 128);
}

// ---------------- kernel 2: RoPE + tf32 split + cache writeback ------------
__global__ __launch_bounds__(256) void k_rope(
    const int* __restrict__ positions,
    const int* __restrict__ widx,
    float* __restrict__ out_kc,
    float* __restrict__ out_vc)
{
    const int t = blockIdx.x;
    __shared__ float cs[64], sn[64];
    const int pos = positions[t];
    if (threadIdx.x < 64) {
        int i = threadIdx.x;
        double e = -((double)(2 * i) / 128.0);
        float inv = (float)pow(500000.0, e);
        float ang = (float)pos * inv;
        float s, c;
        sincosf(ang, &s, &c);
        cs[i] = c;
        sn[i] = s;
    }
    __syncthreads();

    const float* row = g_QKV + (size_t)t * QKVC;
    const int wi = widx[t];
    const float qscale = 0.08838834764831845f;  // 128^-0.5

    for (int idx = threadIdx.x; idx < NQ * 64; idx += blockDim.x) {
        int n = idx >> 6, i = idx & 63;
        float x1 = row[n * HD + i];
        float x2 = row[n * HD + 64 + i];
        float c = cs[i], s = sn[i];
        unsigned* qd = g_Q + ((size_t)n * TSEQ + t) * HD;
        qd[i]      = f2tf((x1 * c - x2 * s) * qscale);
        qd[64 + i] = f2tf((x2 * c + x1 * s) * qscale);
    }
    for (int idx = threadIdx.x; idx < NKV * 64; idx += blockDim.x) {
        int kh = idx >> 6, i = idx & 63;
        float x1 = row[NQ * HD + kh * HD + i];
        float x2 = row[NQ * HD + kh * HD + 64 + i];
        float c = cs[i], s = sn[i];
        float o1 = x1 * c - x2 * s;
        float o2 = x2 * c + x1 * s;
        unsigned* kd = g_K + ((size_t)kh * TSEQ + t) * HD;
        kd[i] = f2tf(o1); kd[64 + i] = f2tf(o2);
        float* kc = out_kc + ((size_t)wi * NKV + kh) * HD;
        kc[i] = o1; kc[64 + i] = o2;    // cache stays exact fp32
    }
    for (int idx = threadIdx.x; idx < NKV * HD; idx += blockDim.x) {
        int kh = idx >> 7, h = idx & 127;
        float v = row[(NQ + NKV) * HD + kh * HD + h];
        g_V[((size_t)kh * TSEQ + t) * HD + h] = f2tf(v);
        out_vc[((size_t)wi * NKV + kh) * HD + h] = v;   // exact fp32
    }
}

// ---------------- kernel 3: tf32-mma causal flash attention ----------------
// grid = (T/64, NQ), 128 threads (4 warps). Warp w owns query rows w*16..+15.
// Q/K/V arrive as tf32 bits; no conversions in the main loop.
// smem words: Qs[64][132] @0, Ks[64][132] @8448 (aliased by Ps[64][68]),
//             Vs[64][132] @16896, PKs[64] @25344
#define ATTN2_SMEM_FLOATS (8448 * 3 + 64)
__global__ __launch_bounds__(128) void k_attn_mma(const int* __restrict__ positions)
{
    extern __shared__ float sm[];
    unsigned* Qs  = (unsigned*)sm;
    unsigned* Ks  = (unsigned*)(sm + 8448);
    unsigned* Vs  = (unsigned*)(sm + 16896);
    int*      PKs = (int*)(sm + 25344);
    unsigned* Ps  = Ks;               // alias (Ks dead once S is computed)

    const int n    = blockIdx.y;
    const int kh   = n >> 2;
    const int t0   = blockIdx.x * 64;
    const int tid  = threadIdx.x;
    const int lane = tid & 31;
    const int w    = tid >> 5;
    const int g    = lane >> 2;
    const int t    = lane & 3;

    const unsigned* Qg = g_Q + ((size_t)n * TSEQ + t0) * HD;
    for (int i = tid; i < 2048; i += 128) {
        int r = i >> 5, c = (i & 31) << 2;
        *(uint4*)(Qs + r * 132 + c) = *(const uint4*)(Qg + (size_t)r * HD + c);
    }

    const int row0 = w * 16 + g;
    const int pq0 = positions[t0 + row0];
    const int pq1 = positions[t0 + row0 + 8];

    float m0 = -1e30f, m1 = -1e30f, l0 = 0.f, l1 = 0.f;
    float o[16][4];
#pragma unroll
    for (int nt = 0; nt < 16; nt++)
#pragma unroll
        for (int i = 0; i < 4; i++) o[nt][i] = 0.f;

    const unsigned* Kg = g_K + (size_t)kh * TSEQ * HD;
    const unsigned* Vg = g_V + (size_t)kh * TSEQ * HD;

    const int nchunks = blockIdx.x + 1;
    for (int ch = 0; ch < nchunks; ch++) {
        const int s0 = ch * 64;
        __syncthreads();

        for (int i = tid; i < 2048; i += 128) {
            int r = i >> 5, c = (i & 31) << 2;
            *(uint4*)(Ks + r * 132 + c) = *(const uint4*)(Kg + (size_t)(s0 + r) * HD + c);
            *(uint4*)(Vs + r * 132 + c) = *(const uint4*)(Vg + (size_t)(s0 + r) * HD + c);
        }
        if (tid < 64) PKs[tid] = positions[s0 + tid];
        __syncthreads();

        // ---- S = Q K^T (64x64), single-pass tf32 ----
        float s[8][4];
#pragma unroll
        for (int nt = 0; nt < 8; nt++)
#pragma unroll
            for (int i = 0; i < 4; i++) s[nt][i] = 0.f;

#pragma unroll
        for (int ks = 0; ks < 16; ks++) {
            const int k0 = ks * 8;
            const unsigned* qp = Qs + row0 * 132 + k0;
            unsigned a[4] = {qp[t], qp[8 * 132 + t], qp[t + 4], qp[8 * 132 + t + 4]};
#pragma unroll
            for (int nt = 0; nt < 8; nt++) {
                const unsigned* kp = Ks + (nt * 8 + g) * 132 + k0;
                unsigned bb[2] = {kp[t], kp[t + 4]};
                mma_tf32(s[nt], a, bb);
            }
        }

        // ---- mask + online softmax ----
        float mx0 = -1e30f, mx1 = -1e30f;
#pragma unroll
        for (int nt = 0; nt < 8; nt++) {
            const int col = nt * 8 + 2 * t;
            int2 pk = *(const int2*)(PKs + col);
            if (pq0 < pk.x) s[nt][0] = -1e30f;
            if (pq0 < pk.y) s[nt][1] = -1e30f;
            if (pq1 < pk.x) s[nt][2] = -1e30f;
            if (pq1 < pk.y) s[nt][3] = -1e30f;
            mx0 = fmaxf(mx0, fmaxf(s[nt][0], s[nt][1]));
            mx1 = fmaxf(mx1, fmaxf(s[nt][2], s[nt][3]));
        }
        mx0 = fmaxf(mx0, __shfl_xor_sync(0xffffffffu, mx0, 1));
        mx0 = fmaxf(mx0, __shfl_xor_sync(0xffffffffu, mx0, 2));
        mx1 = fmaxf(mx1, __shfl_xor_sync(0xffffffffu, mx1, 1));
        mx1 = fmaxf(mx1, __shfl_xor_sync(0xffffffffu, mx1, 2));

        const float mn0 = fmaxf(m0, mx0), mn1 = fmaxf(m1, mx1);
        const float c0 = __expf(m0 - mn0), c1 = __expf(m1 - mn1);
        m0 = mn0; m1 = mn1;

        float sum0 = 0.f, sum1 = 0.f;
#pragma unroll
        for (int nt = 0; nt < 8; nt++) {
            s[nt][0] = __expf(s[nt][0] - mn0);
            s[nt][1] = __expf(s[nt][1] - mn0);
            s[nt][2] = __expf(s[nt][2] - mn1);
            s[nt][3] = __expf(s[nt][3] - mn1);
            sum0 += s[nt][0] + s[nt][1];
            sum1 += s[nt][2] + s[nt][3];
        }
        sum0 += __shfl_xor_sync(0xffffffffu, sum0, 1);
        sum0 += __shfl_xor_sync(0xffffffffu, sum0, 2);
        sum1 += __shfl_xor_sync(0xffffffffu, sum1, 1);
        sum1 += __shfl_xor_sync(0xffffffffu, sum1, 2);
        l0 = l0 * c0 + sum0;
        l1 = l1 * c1 + sum1;

#pragma unroll
        for (int nt = 0; nt < 16; nt++) {
            o[nt][0] *= c0; o[nt][1] *= c0;
            o[nt][2] *= c1; o[nt][3] *= c1;
        }

        __syncthreads();   // all warps done reading Ks before Ps overwrite

        // ---- stage P (tf32 bits); each warp writes/reads only its rows ----
#pragma unroll
        for (int nt = 0; nt < 8; nt++) {
            const int col = nt * 8 + 2 * t;
            uint2 p01 = {f2tf(s[nt][0]), f2tf(s[nt][1])};
            uint2 p23 = {f2tf(s[nt][2]), f2tf(s[nt][3])};
            *(uint2*)(Ps + row0 * 68 + col)       = p01;
            *(uint2*)(Ps + (row0 + 8) * 68 + col) = p23;
        }
        __syncwarp();

        // ---- O += P V ----
#pragma unroll
        for (int ks = 0; ks < 8; ks++) {
            const int k0 = ks * 8;
            const unsigned* pp = Ps + row0 * 68 + k0;
            unsigned a[4] = {pp[t], pp[8 * 68 + t], pp[t + 4], pp[8 * 68 + t + 4]};
#pragma unroll
            for (int nt = 0; nt < 16; nt++) {
                const unsigned* vp = Vs + (k0 + t) * 132 + nt * 8 + g;
                unsigned bb[2] = {vp[0], vp[4 * 132]};
                mma_tf32(o[nt], a, bb);
            }
        }
    }

    // ---- epilogue: write tf32 bits (feeds k_gemm_o directly) ----
    const float inv0 = 1.f / l0, inv1 = 1.f / l1;
    unsigned* outr0 = g_A2 + (size_t)(t0 + row0) * DDIM + n * HD;
    unsigned* outr1 = g_A2 + (size_t)(t0 + row0 + 8) * DDIM + n * HD;
#pragma unroll
    for (int nt = 0; nt < 16; nt++) {
        const int col = nt * 8 + 2 * t;
        uint2 v0 = {f2tf(o[nt][0] * inv0), f2tf(o[nt][1] * inv0)};
        uint2 v1 = {f2tf(o[nt][2] * inv1), f2tf(o[nt][3] * inv1)};
        *(uint2*)(outr0 + col) = v0;
        *(uint2*)(outr1 + col) = v1;
    }
}

// ---------------- kernel 4: output projection ------------------------------
__global__ __launch_bounds__(256) void k_gemm_o(
    const float* __restrict__ wo, float* __restrict__ out_o)
{
    gemm_mma128_t<true>(g_A2, DDIM, wo + (size_t)blockIdx.x * 128, DDIM,
                        out_o + (size_t)blockIdx.x * 128, DDIM,
                        DDIM, blockIdx.y * 128);
}

// ---------------- launch ----------------------------------------------------
extern "C" void kernel_launch(void* const* d_in, const int* in_sizes, int n_in,
                              void* d_out, int out_size)
{
    (void)in_sizes; (void)n_in; (void)out_size;
    const float* x     = (const float*)d_in[0];
    const float* wq    = (const float*)d_in[1];
    const float* wk    = (const float*)d_in[2];
    const float* wv    = (const float*)d_in[3];
    const float* wo    = (const float*)d_in[4];
    const float* kc_in = (const float*)d_in[5];
    const float* vc_in = (const float*)d_in[6];
    const int* positions = (const int*)d_in[7];
    const int* widx      = (const int*)d_in[8];

    float* out_kc = (float*)d_out;
    float* out_vc = out_kc + (size_t)NSLOTS * NKV * HD;
    float* out_o  = out_vc + (size_t)NSLOTS * NKV * HD;

    const size_t cacheBytes = (size_t)NSLOTS * NKV * HD * sizeof(float);
    cudaMemcpyAsync(out_kc, kc_in, cacheBytes, cudaMemcpyDeviceToDevice, 0);
    cudaMemcpyAsync(out_vc, vc_in, cacheBytes, cudaMemcpyDeviceToDevice, 0);

    k_gemm_qkv<<<dim3(48, TSEQ / 128), 256, 0, 0>>>(x, wq, wk, wv);
    k_rope<<<TSEQ, 256, 0, 0>>>(positions, widx, out_kc, out_vc);

    const int attn_smem = ATTN2_SMEM_FLOATS * (int)sizeof(float);
    cudaFuncSetAttribute(k_attn_mma,
                         cudaFuncAttributeMaxDynamicSharedMemorySize, attn_smem);
    k_attn_mma<<<dim3(TSEQ / 64, NQ), 128, attn_smem, 0>>>(positions);

    k_gemm_o<<<dim3(DDIM / 128, TSEQ / 128), 256, 0, 0>>>(wo, out_o);
}

// round 8
// speedup vs baseline: 1.0762x; 1.0336x over previous
#include <cuda_runtime.h>
#include <cstdint>
#include <stdint.h>
#include <math.h>

// Problem constants (fixed by the dataset)
#define TSEQ   2048
#define DDIM   4096
#define NQ     32
#define NKV    8
#define HD     128
#define NSLOTS 32768
#define QKVC   6144   // 32*128 + 8*128 + 8*128

// ---------------- scratch (static device allocations; no cudaMalloc) -------
__device__ float    g_QKV[(size_t)TSEQ * QKVC];      // [t][6144] fp32
__device__ unsigned g_Q  [(size_t)NQ  * TSEQ * HD];  // [n][t][h] tf32 bits (scaled)
__device__ unsigned g_K  [(size_t)NKV * TSEQ * HD];  // [kh][t][h] tf32 bits
__device__ unsigned g_V  [(size_t)NKV * TSEQ * HD];  // [kh][t][h] tf32 bits
__device__ unsigned g_A2 [(size_t)TSEQ * DDIM];      // [t][n*128+h] tf32 bits

// ---------------- tf32 mma helpers -----------------------------------------
__device__ __forceinline__ unsigned f2tf(float x) {
    unsigned r;
    asm("cvt.rna.tf32.f32 %0, %1;" : "=r"(r) : "f"(x));
    return r;
}

__device__ __forceinline__ void mma_tf32(float* d, const unsigned* a,
                                         const unsigned* b) {
    asm volatile(
        "mma.sync.aligned.m16n8k8.row.col.f32.tf32.tf32.f32 "
        "{%0,%1,%2,%3}, {%4,%5,%6,%7}, {%8,%9}, {%0,%1,%2,%3};"
        : "+f"(d[0]), "+f"(d[1]), "+f"(d[2]), "+f"(d[3])
        : "r"(a[0]), "r"(a[1]), "r"(a[2]), "r"(a[3]), "r"(b[0]), "r"(b[1]));
}

__device__ __forceinline__ void cp16(unsigned smem, const void* g) {
    asm volatile("cp.async.cg.shared.global [%0], [%1], 16;\n"
                 :: "r"(smem), "l"(g));
}

// ---------------- 128x128 tf32 GEMM, 4 warps, 64x64 warp tile --------------
// 3-stage single-sync pipeline; LDS:MMA ratio 1.0 (crossbar-optimized).
// A: row-major [.., lda] — tf32 BITS if ABITS else FP32 (cvt at frag load).
// B: row-major FP32 [Kdim, ldb] (cvt at frag load).
// 128 threads (4 warps 2x2). Kdim % 16 == 0.
template <bool ABITS>
__device__ __forceinline__ void gemm_mma128_t(
    const void* __restrict__ Av, int lda,
    const float* __restrict__ B, int ldb,
    float* __restrict__ C, int ldc,
    int Kdim, int rowBase)
{
    __shared__ unsigned As[3][128][20];   // pad 20
    __shared__ float    Bs[3][16][136];   // pad 136

    const int tid  = threadIdx.x;
    const int lane = tid & 31;
    const int warp = tid >> 5;
    const int wM   = warp >> 1;        // 0..1 -> 64-row slab
    const int wN   = warp & 1;         // 0..1 -> 64-col slab
    const int g    = lane >> 2;        // 0..7
    const int t    = lane & 3;         // 0..3

    const int ar = tid >> 2, ac = (tid & 3) << 2;   // A ld: 32 rows x 4 f4 per pass
    const int br = tid >> 5, bc = (tid & 31) << 2;  // B ld: 4 rows x 32 f4 per pass

    const char* Ab = (const char*)Av + (size_t)rowBase * lda * 4;

    float acc[4][8][4];
#pragma unroll
    for (int mt = 0; mt < 4; mt++)
#pragma unroll
        for (int nt = 0; nt < 8; nt++)
#pragma unroll
            for (int i = 0; i < 4; i++) acc[mt][nt][i] = 0.f;

    const unsigned sA0 = (unsigned)__cvta_generic_to_shared(&As[0][0][0]);
    const unsigned sB0 = (unsigned)__cvta_generic_to_shared(&Bs[0][0][0]);
    const unsigned stASz = (unsigned)(128 * 20 * 4);
    const unsigned stBSz = (unsigned)(16 * 136 * 4);

    const int niter = Kdim >> 4;

    // ---- prologue: stages 0,1 ----
#pragma unroll
    for (int p = 0; p < 2; p++) {
        const int k0 = p << 4;
        const unsigned stA = sA0 + (unsigned)p * stASz;
        const unsigned stB = sB0 + (unsigned)p * stBSz;
#pragma unroll
        for (int q = 0; q < 4; q++) {
            cp16(stA + (unsigned)((ar + q * 32) * 20 + ac) * 4u,
                 Ab + ((size_t)(ar + q * 32) * lda + k0 + ac) * 4);
            cp16(stB + (unsigned)((br + q * 4) * 136 + bc) * 4u,
                 B + (size_t)(k0 + br + q * 4) * ldb + bc);
        }
        asm volatile("cp.async.commit_group;");
    }

    for (int it = 0; it < niter; it++) {
        asm volatile("cp.async.wait_group 1;");
        __syncthreads();   // stage `it` ready; stage it-1 fully consumed

        // issue stage it+2 into buffer (it+2)%3
        if (it + 2 < niter) {
            const int k0 = (it + 2) << 4;
            const int bsel = (it + 2) % 3;
            const unsigned stA = sA0 + (unsigned)bsel * stASz;
            const unsigned stB = sB0 + (unsigned)bsel * stBSz;
#pragma unroll
            for (int q = 0; q < 4; q++) {
                cp16(stA + (unsigned)((ar + q * 32) * 20 + ac) * 4u,
                     Ab + ((size_t)(ar + q * 32) * lda + k0 + ac) * 4);
                cp16(stB + (unsigned)((br + q * 4) * 136 + bc) * 4u,
                     B + (size_t)(k0 + br + q * 4) * ldb + bc);
            }
        }
        asm volatile("cp.async.commit_group;");

        const int st = it % 3;
#pragma unroll
        for (int ks = 0; ks < 2; ks++) {
            unsigned af[4][4], bf[8][2];
#pragma unroll
            for (int mt = 0; mt < 4; mt++) {
                const unsigned* p = &As[st][wM * 64 + mt * 16 + g][ks * 8 + t];
                if (ABITS) {
                    af[mt][0] = p[0];
                    af[mt][1] = p[8 * 20];
                    af[mt][2] = p[4];
                    af[mt][3] = p[8 * 20 + 4];
                } else {
                    af[mt][0] = f2tf(__uint_as_float(p[0]));
                    af[mt][1] = f2tf(__uint_as_float(p[8 * 20]));
                    af[mt][2] = f2tf(__uint_as_float(p[4]));
                    af[mt][3] = f2tf(__uint_as_float(p[8 * 20 + 4]));
                }
            }
#pragma unroll
            for (int nt = 0; nt < 8; nt++) {
                bf[nt][0] = f2tf(Bs[st][ks * 8 + t    ][wN * 64 + nt * 8 + g]);
                bf[nt][1] = f2tf(Bs[st][ks * 8 + t + 4][wN * 64 + nt * 8 + g]);
            }
#pragma unroll
            for (int mt = 0; mt < 4; mt++)
#pragma unroll
                for (int nt = 0; nt < 8; nt++)
                    mma_tf32(acc[mt][nt], af[mt], bf[nt]);
        }
    }

#pragma unroll
    for (int mt = 0; mt < 4; mt++) {
#pragma unroll
        for (int nt = 0; nt < 8; nt++) {
            const int r0 = rowBase + wM * 64 + mt * 16 + g;
            const int c0 = wN * 64 + nt * 8 + 2 * t;
            float2 v0 = {acc[mt][nt][0], acc[mt][nt][1]};
            float2 v1 = {acc[mt][nt][2], acc[mt][nt][3]};
            *(float2*)(C + (size_t)r0 * ldc + c0)       = v0;
            *(float2*)(C + (size_t)(r0 + 8) * ldc + c0) = v1;
        }
    }
}

// ---------------- kernel 1: fused QKV projection ---------------------------
__global__ __launch_bounds__(128) void k_gemm_qkv(
    const float* __restrict__ x,
    const float* __restrict__ wq,
    const float* __restrict__ wk,
    const float* __restrict__ wv)
{
    int cb = blockIdx.x;
    const float* B;
    if (cb < 32)      B = wq + (size_t)cb * DDIM * HD;
    else if (cb < 40) B = wk + (size_t)(cb - 32) * DDIM * HD;
    else              B = wv + (size_t)(cb - 40) * DDIM * HD;
    gemm_mma128_t<false>(x, DDIM, B, HD, g_QKV + (size_t)cb * HD, QKVC,
                         DDIM, blockIdx.y * 128);
}

// ---------------- kernel 2: RoPE + tf32 split + cache writeback ------------
__global__ __launch_bounds__(256) void k_rope(
    const int* __restrict__ positions,
    const int* __restrict__ widx,
    float* __restrict__ out_kc,
    float* __restrict__ out_vc)
{
    const int t = blockIdx.x;
    __shared__ float cs[64], sn[64];
    const int pos = positions[t];
    if (threadIdx.x < 64) {
        int i = threadIdx.x;
        double e = -((double)(2 * i) / 128.0);
        float inv = (float)pow(500000.0, e);
        float ang = (float)pos * inv;
        float s, c;
        sincosf(ang, &s, &c);
        cs[i] = c;
        sn[i] = s;
    }
    __syncthreads();

    const float* row = g_QKV + (size_t)t * QKVC;
    const int wi = widx[t];
    const float qscale = 0.08838834764831845f;  // 128^-0.5

    for (int idx = threadIdx.x; idx < NQ * 64; idx += blockDim.x) {
        int n = idx >> 6, i = idx & 63;
        float x1 = row[n * HD + i];
        float x2 = row[n * HD + 64 + i];
        float c = cs[i], s = sn[i];
        unsigned* qd = g_Q + ((size_t)n * TSEQ + t) * HD;
        qd[i]      = f2tf((x1 * c - x2 * s) * qscale);
        qd[64 + i] = f2tf((x2 * c + x1 * s) * qscale);
    }
    for (int idx = threadIdx.x; idx < NKV * 64; idx += blockDim.x) {
        int kh = idx >> 6, i = idx & 63;
        float x1 = row[NQ * HD + kh * HD + i];
        float x2 = row[NQ * HD + kh * HD + 64 + i];
        float c = cs[i], s = sn[i];
        float o1 = x1 * c - x2 * s;
        float o2 = x2 * c + x1 * s;
        unsigned* kd = g_K + ((size_t)kh * TSEQ + t) * HD;
        kd[i] = f2tf(o1); kd[64 + i] = f2tf(o2);
        float* kc = out_kc + ((size_t)wi * NKV + kh) * HD;
        kc[i] = o1; kc[64 + i] = o2;    // cache stays exact fp32
    }
    for (int idx = threadIdx.x; idx < NKV * HD; idx += blockDim.x) {
        int kh = idx >> 7, h = idx & 127;
        float v = row[(NQ + NKV) * HD + kh * HD + h];
        g_V[((size_t)kh * TSEQ + t) * HD + h] = f2tf(v);
        out_vc[((size_t)wi * NKV + kh) * HD + h] = v;   // exact fp32
    }
}

// ---------------- kernel 3: tf32-mma causal flash attention ----------------
#define ATTN2_SMEM_FLOATS (8448 * 3 + 64)
__global__ __launch_bounds__(128) void k_attn_mma(const int* __restrict__ positions)
{
    extern __shared__ float sm[];
    unsigned* Qs  = (unsigned*)sm;
    unsigned* Ks  = (unsigned*)(sm + 8448);
    unsigned* Vs  = (unsigned*)(sm + 16896);
    int*      PKs = (int*)(sm + 25344);
    unsigned* Ps  = Ks;               // alias (Ks dead once S is computed)

    const int n    = blockIdx.y;
    const int kh   = n >> 2;
    const int t0   = blockIdx.x * 64;
    const int tid  = threadIdx.x;
    const int lane = tid & 31;
    const int w    = tid >> 5;
    const int g    = lane >> 2;
    const int t    = lane & 3;

    const unsigned* Qg = g_Q + ((size_t)n * TSEQ + t0) * HD;
    for (int i = tid; i < 2048; i += 128) {
        int r = i >> 5, c = (i & 31) << 2;
        *(uint4*)(Qs + r * 132 + c) = *(const uint4*)(Qg + (size_t)r * HD + c);
    }

    const int row0 = w * 16 + g;
    const int pq0 = positions[t0 + row0];
    const int pq1 = positions[t0 + row0 + 8];

    float m0 = -1e30f, m1 = -1e30f, l0 = 0.f, l1 = 0.f;
    float o[16][4];
#pragma unroll
    for (int nt = 0; nt < 16; nt++)
#pragma unroll
        for (int i = 0; i < 4; i++) o[nt][i] = 0.f;

    const unsigned* Kg = g_K + (size_t)kh * TSEQ * HD;
    const unsigned* Vg = g_V + (size_t)kh * TSEQ * HD;

    const int nchunks = blockIdx.x + 1;
    for (int ch = 0; ch < nchunks; ch++) {
        const int s0 = ch * 64;
        __syncthreads();

        for (int i = tid; i < 2048; i += 128) {
            int r = i >> 5, c = (i & 31) << 2;
            *(uint4*)(Ks + r * 132 + c) = *(const uint4*)(Kg + (size_t)(s0 + r) * HD + c);
            *(uint4*)(Vs + r * 132 + c) = *(const uint4*)(Vg + (size_t)(s0 + r) * HD + c);
        }
        if (tid < 64) PKs[tid] = positions[s0 + tid];
        __syncthreads();

        // ---- S = Q K^T (64x64), single-pass tf32 ----
        float s[8][4];
#pragma unroll
        for (int nt = 0; nt < 8; nt++)
#pragma unroll
            for (int i = 0; i < 4; i++) s[nt][i] = 0.f;

#pragma unroll
        for (int ks = 0; ks < 16; ks++) {
            const int k0 = ks * 8;
            const unsigned* qp = Qs + row0 * 132 + k0;
            unsigned a[4] = {qp[t], qp[8 * 132 + t], qp[t + 4], qp[8 * 132 + t + 4]};
#pragma unroll
            for (int nt = 0; nt < 8; nt++) {
                const unsigned* kp = Ks + (nt * 8 + g) * 132 + k0;
                unsigned bb[2] = {kp[t], kp[t + 4]};
                mma_tf32(s[nt], a, bb);
            }
        }

        // ---- mask + online softmax ----
        float mx0 = -1e30f, mx1 = -1e30f;
#pragma unroll
        for (int nt = 0; nt < 8; nt++) {
            const int col = nt * 8 + 2 * t;
            int2 pk = *(const int2*)(PKs + col);
            if (pq0 < pk.x) s[nt][0] = -1e30f;
            if (pq0 < pk.y) s[nt][1] = -1e30f;
            if (pq1 < pk.x) s[nt][2] = -1e30f;
            if (pq1 < pk.y) s[nt][3] = -1e30f;
            mx0 = fmaxf(mx0, fmaxf(s[nt][0], s[nt][1]));
            mx1 = fmaxf(mx1, fmaxf(s[nt][2], s[nt][3]));
        }
        mx0 = fmaxf(mx0, __shfl_xor_sync(0xffffffffu, mx0, 1));
        mx0 = fmaxf(mx0, __shfl_xor_sync(0xffffffffu, mx0, 2));
        mx1 = fmaxf(mx1, __shfl_xor_sync(0xffffffffu, mx1, 1));
        mx1 = fmaxf(mx1, __shfl_xor_sync(0xffffffffu, mx1, 2));

        const float mn0 = fmaxf(m0, mx0), mn1 = fmaxf(m1, mx1);
        const float c0 = __expf(m0 - mn0), c1 = __expf(m1 - mn1);
        m0 = mn0; m1 = mn1;

        float sum0 = 0.f, sum1 = 0.f;
#pragma unroll
        for (int nt = 0; nt < 8; nt++) {
            s[nt][0] = __expf(s[nt][0] - mn0);
            s[nt][1] = __expf(s[nt][1] - mn0);
            s[nt][2] = __expf(s[nt][2] - mn1);
            s[nt][3] = __expf(s[nt][3] - mn1);
            sum0 += s[nt][0] + s[nt][1];
            sum1 += s[nt][2] + s[nt][3];
        }
        sum0 += __shfl_xor_sync(0xffffffffu, sum0, 1);
        sum0 += __shfl_xor_sync(0xffffffffu, sum0, 2);
        sum1 += __shfl_xor_sync(0xffffffffu, sum1, 1);
        sum1 += __shfl_xor_sync(0xffffffffu, sum1, 2);
        l0 = l0 * c0 + sum0;
        l1 = l1 * c1 + sum1;

#pragma unroll
        for (int nt = 0; nt < 16; nt++) {
            o[nt][0] *= c0; o[nt][1] *= c0;
            o[nt][2] *= c1; o[nt][3] *= c1;
        }

        __syncthreads();   // all warps done reading Ks before Ps overwrite

#pragma unroll
        for (int nt = 0; nt < 8; nt++) {
            const int col = nt * 8 + 2 * t;
            uint2 p01 = {f2tf(s[nt][0]), f2tf(s[nt][1])};
            uint2 p23 = {f2tf(s[nt][2]), f2tf(s[nt][3])};
            *(uint2*)(Ps + row0 * 68 + col)       = p01;
            *(uint2*)(Ps + (row0 + 8) * 68 + col) = p23;
        }
        __syncwarp();

#pragma unroll
        for (int ks = 0; ks < 8; ks++) {
            const int k0 = ks * 8;
            const unsigned* pp = Ps + row0 * 68 + k0;
            unsigned a[4] = {pp[t], pp[8 * 68 + t], pp[t + 4], pp[8 * 68 + t + 4]};
#pragma unroll
            for (int nt = 0; nt < 16; nt++) {
                const unsigned* vp = Vs + (k0 + t) * 132 + nt * 8 + g;
                unsigned bb[2] = {vp[0], vp[4 * 132]};
                mma_tf32(o[nt], a, bb);
            }
        }
    }

    // ---- epilogue: write tf32 bits (feeds k_gemm_o directly) ----
    const float inv0 = 1.f / l0, inv1 = 1.f / l1;
    unsigned* outr0 = g_A2 + (size_t)(t0 + row0) * DDIM + n * HD;
    unsigned* outr1 = g_A2 + (size_t)(t0 + row0 + 8) * DDIM + n * HD;
#pragma unroll
    for (int nt = 0; nt < 16; nt++) {
        const int col = nt * 8 + 2 * t;
        uint2 v0 = {f2tf(o[nt][0] * inv0), f2tf(o[nt][1] * inv0)};
        uint2 v1 = {f2tf(o[nt][2] * inv1), f2tf(o[nt][3] * inv1)};
        *(uint2*)(outr0 + col) = v0;
        *(uint2*)(outr1 + col) = v1;
    }
}

// ---------------- kernel 4: output projection ------------------------------
__global__ __launch_bounds__(128) void k_gemm_o(
    const float* __restrict__ wo, float* __restrict__ out_o)
{
    gemm_mma128_t<true>(g_A2, DDIM, wo + (size_t)blockIdx.x * 128, DDIM,
                        out_o + (size_t)blockIdx.x * 128, DDIM,
                        DDIM, blockIdx.y * 128);
}

// ---------------- launch ----------------------------------------------------
extern "C" void kernel_launch(void* const* d_in, const int* in_sizes, int n_in,
                              void* d_out, int out_size)
{
    (void)in_sizes; (void)n_in; (void)out_size;
    const float* x     = (const float*)d_in[0];
    const float* wq    = (const float*)d_in[1];
    const float* wk    = (const float*)d_in[2];
    const float* wv    = (const float*)d_in[3];
    const float* wo    = (const float*)d_in[4];
    const float* kc_in = (const float*)d_in[5];
    const float* vc_in = (const float*)d_in[6];
    const int* positions = (const int*)d_in[7];
    const int* widx      = (const int*)d_in[8];

    float* out_kc = (float*)d_out;
    float* out_vc = out_kc + (size_t)NSLOTS * NKV * HD;
    float* out_o  = out_vc + (size_t)NSLOTS * NKV * HD;

    // side stream + events for cache-copy overlap (created once, on the
    // uncaptured correctness call; reused by the captured graph)
    static cudaStream_t s2 = nullptr;
    static cudaEvent_t  e1 = nullptr, e2 = nullptr;
    if (!s2) {
        cudaStreamCreateWithFlags(&s2, cudaStreamNonBlocking);
        cudaEventCreateWithFlags(&e1, cudaEventDisableTiming);
        cudaEventCreateWithFlags(&e2, cudaEventDisableTiming);
    }

    const size_t cacheBytes = (size_t)NSLOTS * NKV * HD * sizeof(float);

    // fork: cache copies run on s2, concurrent with the QKV GEMM
    cudaEventRecord(e1, 0);
    cudaStreamWaitEvent(s2, e1, 0);
    cudaMemcpyAsync(out_kc, kc_in, cacheBytes, cudaMemcpyDeviceToDevice, s2);
    cudaMemcpyAsync(out_vc, vc_in, cacheBytes, cudaMemcpyDeviceToDevice, s2);
    cudaEventRecord(e2, s2);

    k_gemm_qkv<<<dim3(48, TSEQ / 128), 128, 0, 0>>>(x, wq, wk, wv);

    // join: rope overwrites cache rows, must follow the copies
    cudaStreamWaitEvent(0, e2, 0);
    k_rope<<<TSEQ, 256, 0, 0>>>(positions, widx, out_kc, out_vc);

    const int attn_smem = ATTN2_SMEM_FLOATS * (int)sizeof(float);
    cudaFuncSetAttribute(k_attn_mma,
                         cudaFuncAttributeMaxDynamicSharedMemorySize, attn_smem);
    k_attn_mma<<<dim3(TSEQ / 64, NQ), 128, attn_smem, 0>>>(positions);

    k_gemm_o<<<dim3(DDIM / 128, TSEQ / 128), 128, 0, 0>>>(wo, out_o);
}

// round 9
// speedup vs baseline: 1.5105x; 1.4035x over previous
#include <cuda_runtime.h>
#include <cuda_fp16.h>
#include <cstdint>
#include <stdint.h>
#include <math.h>

// Problem constants (fixed by the dataset)
#define TSEQ   2048
#define DDIM   4096
#define NQ     32
#define NKV    8
#define HD     128
#define NSLOTS 32768
#define QKVC   6144   // 32*128 + 8*128 + 8*128

// Packed-weight offsets (uint = half2 elements), pack along K
#define WQP_ELEMS ((size_t)NQ  * (DDIM / 2) * HD)   // 8.39M
#define WKP_ELEMS ((size_t)NKV * (DDIM / 2) * HD)   // 2.10M
#define WOP_ELEMS ((size_t)(DDIM / 2) * DDIM)       // 8.39M
#define WQP_OFF   ((size_t)0)
#define WKP_OFF   (WQP_OFF + WQP_ELEMS)
#define WVP_OFF   (WKP_OFF + WKP_ELEMS)
#define WOP_OFF   (WVP_OFF + WKP_ELEMS)

// ---------------- scratch (static device allocations; no cudaMalloc) -------
__device__ float    g_QKV[(size_t)TSEQ * QKVC];      // [t][6144] fp32
__device__ unsigned g_Q  [(size_t)NQ  * TSEQ * HD];  // [n][t][h] tf32 bits (scaled)
__device__ unsigned g_K  [(size_t)NKV * TSEQ * HD];  // [kh][t][h] tf32 bits
__device__ unsigned g_V  [(size_t)NKV * TSEQ * HD];  // [kh][t][h] tf32 bits
__device__ __half   g_A2h[(size_t)TSEQ * DDIM];      // [t][n*128+h] fp16
__device__ __half   g_Xh [(size_t)TSEQ * DDIM];      // x fp16 (A-side)
__device__ unsigned g_Wp [WOP_OFF + WOP_ELEMS];      // packed half2 weights

// ---------------- mma helpers -----------------------------------------------
__device__ __forceinline__ unsigned f2tf(float x) {
    unsigned r;
    asm("cvt.rna.tf32.f32 %0, %1;" : "=r"(r) : "f"(x));
    return r;
}

__device__ __forceinline__ void mma_tf32(float* d, const unsigned* a,
                                         const unsigned* b) {
    asm volatile(
        "mma.sync.aligned.m16n8k8.row.col.f32.tf32.tf32.f32 "
        "{%0,%1,%2,%3}, {%4,%5,%6,%7}, {%8,%9}, {%0,%1,%2,%3};"
        : "+f"(d[0]), "+f"(d[1]), "+f"(d[2]), "+f"(d[3])
        : "r"(a[0]), "r"(a[1]), "r"(a[2]), "r"(a[3]), "r"(b[0]), "r"(b[1]));
}

__device__ __forceinline__ void mma_f16(float* d, const unsigned* a,
                                        const unsigned* b) {
    asm volatile(
        "mma.sync.aligned.m16n8k16.row.col.f32.f16.f16.f32 "
        "{%0,%1,%2,%3}, {%4,%5,%6,%7}, {%8,%9}, {%0,%1,%2,%3};"
        : "+f"(d[0]), "+f"(d[1]), "+f"(d[2]), "+f"(d[3])
        : "r"(a[0]), "r"(a[1]), "r"(a[2]), "r"(a[3]), "r"(b[0]), "r"(b[1]));
}

__device__ __forceinline__ void cp16(unsigned smem, const void* g) {
    asm volatile("cp.async.cg.shared.global [%0], [%1], 16;\n"
                 :: "r"(smem), "l"(g));
}

__device__ __forceinline__ unsigned pack_h2(float a, float b) {
    __half2 h = __floats2half2_rn(a, b);
    return *(unsigned*)&h;
}

// ---------------- prep kernels ---------------------------------------------
// x fp32 -> fp16 (A-side, plain row-major)
__global__ __launch_bounds__(256) void k_cvt_half(
    const float4* __restrict__ in, uint2* __restrict__ out, int n4)
{
    int i = blockIdx.x * 256 + threadIdx.x;
    if (i < n4) {
        float4 v = in[i];
        uint2 o = {pack_h2(v.x, v.y), pack_h2(v.z, v.w)};
        out[i] = o;
    }
}

// weights fp32 [2*K2][N] -> packed half2 [K2][N] (pack adjacent K rows)
__global__ __launch_bounds__(256) void k_pack_half(
    const float* __restrict__ in, unsigned* __restrict__ out, int K2, int N)
{
    int i = blockIdx.x * 256 + threadIdx.x;
    if (i < K2 * N) {
        int k2 = i / N, n = i - k2 * N;
        out[i] = pack_h2(in[(size_t)(2 * k2) * N + n],
                         in[(size_t)(2 * k2 + 1) * N + n]);
    }
}

// ---------------- 128x128 fp16 GEMM, 4 warps, 64x64 warp tile --------------
// A: fp16 row-major [.., lda] (lda in halves). B: packed half2 [K/2][ldbp]
// (ldbp in uint). 3-stage single-sync cp.async pipeline. BK=32 halves.
// 128 threads (4 warps 2x2). Kdim (halves) % 32 == 0.
__device__ __forceinline__ void gemm_mma128_h(
    const __half* __restrict__ A, int lda,
    const unsigned* __restrict__ Bp, int ldbp,
    float* __restrict__ C, int ldc,
    int Kdim, int rowBase)
{
    __shared__ unsigned As[3][128][20];   // 16 half2 used per row; pad 20
    __shared__ unsigned Bs[3][16][136];   // 128 uint per row; pad 136

    const int tid  = threadIdx.x;
    const int lane = tid & 31;
    const int warp = tid >> 5;
    const int wM   = warp >> 1;        // 0..1 -> 64-row slab
    const int wN   = warp & 1;         // 0..1 -> 64-col slab
    const int g    = lane >> 2;        // 0..7
    const int t    = lane & 3;         // 0..3

    const int ar = tid >> 2, ac = (tid & 3) << 2;   // A: 32 rows x 4 uint
    const int br = tid >> 5, bc = (tid & 31) << 2;  // B: 4 rows x 32 uint

    const __half* Ab = A + (size_t)rowBase * lda;

    float acc[4][8][4];
#pragma unroll
    for (int mt = 0; mt < 4; mt++)
#pragma unroll
        for (int nt = 0; nt < 8; nt++)
#pragma unroll
            for (int i = 0; i < 4; i++) acc[mt][nt][i] = 0.f;

    const unsigned sA0 = (unsigned)__cvta_generic_to_shared(&As[0][0][0]);
    const unsigned sB0 = (unsigned)__cvta_generic_to_shared(&Bs[0][0][0]);
    const unsigned stASz = (unsigned)(128 * 20 * 4);
    const unsigned stBSz = (unsigned)(16 * 136 * 4);

    const int niter = Kdim >> 5;   // BK = 32 halves

    // ---- prologue: stages 0,1 ----
#pragma unroll
    for (int p = 0; p < 2; p++) {
        const int k0 = p << 5;               // half offset
        const int k20 = k0 >> 1;             // packed-row offset
        const unsigned stA = sA0 + (unsigned)p * stASz;
        const unsigned stB = sB0 + (unsigned)p * stBSz;
#pragma unroll
        for (int q = 0; q < 4; q++) {
            cp16(stA + (unsigned)((ar + q * 32) * 20 + ac) * 4u,
                 Ab + (size_t)(ar + q * 32) * lda + k0 + ac * 2);
            cp16(stB + (unsigned)((br + q * 4) * 136 + bc) * 4u,
                 Bp + (size_t)(k20 + br + q * 4) * ldbp + bc);
        }
        asm volatile("cp.async.commit_group;");
    }

    for (int it = 0; it < niter; it++) {
        asm volatile("cp.async.wait_group 1;");
        __syncthreads();

        if (it + 2 < niter) {
            const int k0 = (it + 2) << 5;
            const int k20 = k0 >> 1;
            const int bsel = (it + 2) % 3;
            const unsigned stA = sA0 + (unsigned)bsel * stASz;
            const unsigned stB = sB0 + (unsigned)bsel * stBSz;
#pragma unroll
            for (int q = 0; q < 4; q++) {
                cp16(stA + (unsigned)((ar + q * 32) * 20 + ac) * 4u,
                     Ab + (size_t)(ar + q * 32) * lda + k0 + ac * 2);
                cp16(stB + (unsigned)((br + q * 4) * 136 + bc) * 4u,
                     Bp + (size_t)(k20 + br + q * 4) * ldbp + bc);
            }
        }
        asm volatile("cp.async.commit_group;");

        const int st = it % 3;
#pragma unroll
        for (int ks = 0; ks < 2; ks++) {     // two K16 steps per stage
            unsigned af[4][4], bf[8][2];
#pragma unroll
            for (int mt = 0; mt < 4; mt++) {
                const unsigned* p = &As[st][wM * 64 + mt * 16 + g][ks * 8 + t];
                af[mt][0] = p[0];            // (g,   k2=t)
                af[mt][1] = p[8 * 20];       // (g+8, k2=t)
                af[mt][2] = p[4];            // (g,   k2=t+4)
                af[mt][3] = p[8 * 20 + 4];   // (g+8, k2=t+4)
            }
#pragma unroll
            for (int nt = 0; nt < 8; nt++) {
                bf[nt][0] = Bs[st][ks * 8 + t    ][wN * 64 + nt * 8 + g];
                bf[nt][1] = Bs[st][ks * 8 + t + 4][wN * 64 + nt * 8 + g];
            }
#pragma unroll
            for (int mt = 0; mt < 4; mt++)
#pragma unroll
                for (int nt = 0; nt < 8; nt++)
                    mma_f16(acc[mt][nt], af[mt], bf[nt]);
        }
    }

#pragma unroll
    for (int mt = 0; mt < 4; mt++) {
#pragma unroll
        for (int nt = 0; nt < 8; nt++) {
            const int r0 = rowBase + wM * 64 + mt * 16 + g;
            const int c0 = wN * 64 + nt * 8 + 2 * t;
            float2 v0 = {acc[mt][nt][0], acc[mt][nt][1]};
            float2 v1 = {acc[mt][nt][2], acc[mt][nt][3]};
            *(float2*)(C + (size_t)r0 * ldc + c0)       = v0;
            *(float2*)(C + (size_t)(r0 + 8) * ldc + c0) = v1;
        }
    }
}

// ---------------- kernel 1: fused QKV projection ---------------------------
__global__ __launch_bounds__(128) void k_gemm_qkv()
{
    int cb = blockIdx.x;
    const unsigned* Bp;
    if (cb < 32)      Bp = g_Wp + WQP_OFF + (size_t)cb * (DDIM / 2) * HD;
    else if (cb < 40) Bp = g_Wp + WKP_OFF + (size_t)(cb - 32) * (DDIM / 2) * HD;
    else              Bp = g_Wp + WVP_OFF + (size_t)(cb - 40) * (DDIM / 2) * HD;
    gemm_mma128_h(g_Xh, DDIM, Bp, HD, g_QKV + (size_t)cb * HD, QKVC,
                  DDIM, blockIdx.y * 128);
}

// ---------------- kernel 2: RoPE + tf32 split + cache writeback ------------
__global__ __launch_bounds__(256) void k_rope(
    const int* __restrict__ positions,
    const int* __restrict__ widx,
    float* __restrict__ out_kc,
    float* __restrict__ out_vc)
{
    const int t = blockIdx.x;
    __shared__ float cs[64], sn[64];
    const int pos = positions[t];
    if (threadIdx.x < 64) {
        int i = threadIdx.x;
        double e = -((double)(2 * i) / 128.0);
        float inv = (float)pow(500000.0, e);
        float ang = (float)pos * inv;
        float s, c;
        sincosf(ang, &s, &c);
        cs[i] = c;
        sn[i] = s;
    }
    __syncthreads();

    const float* row = g_QKV + (size_t)t * QKVC;
    const int wi = widx[t];
    const float qscale = 0.08838834764831845f;  // 128^-0.5

    for (int idx = threadIdx.x; idx < NQ * 64; idx += blockDim.x) {
        int n = idx >> 6, i = idx & 63;
        float x1 = row[n * HD + i];
        float x2 = row[n * HD + 64 + i];
        float c = cs[i], s = sn[i];
        unsigned* qd = g_Q + ((size_t)n * TSEQ + t) * HD;
        qd[i]      = f2tf((x1 * c - x2 * s) * qscale);
        qd[64 + i] = f2tf((x2 * c + x1 * s) * qscale);
    }
    for (int idx = threadIdx.x; idx < NKV * 64; idx += blockDim.x) {
        int kh = idx >> 6, i = idx & 63;
        float x1 = row[NQ * HD + kh * HD + i];
        float x2 = row[NQ * HD + kh * HD + 64 + i];
        float c = cs[i], s = sn[i];
        float o1 = x1 * c - x2 * s;
        float o2 = x2 * c + x1 * s;
        unsigned* kd = g_K + ((size_t)kh * TSEQ + t) * HD;
        kd[i] = f2tf(o1); kd[64 + i] = f2tf(o2);
        float* kc = out_kc + ((size_t)wi * NKV + kh) * HD;
        kc[i] = o1; kc[64 + i] = o2;    // cache stays exact fp32
    }
    for (int idx = threadIdx.x; idx < NKV * HD; idx += blockDim.x) {
        int kh = idx >> 7, h = idx & 127;
        float v = row[(NQ + NKV) * HD + kh * HD + h];
        g_V[((size_t)kh * TSEQ + t) * HD + h] = f2tf(v);
        out_vc[((size_t)wi * NKV + kh) * HD + h] = v;   // exact fp32
    }
}

// ---------------- kernel 3: tf32-mma causal flash attention ----------------
#define ATTN2_SMEM_FLOATS (8448 * 3 + 64)
__global__ __launch_bounds__(128) void k_attn_mma(const int* __restrict__ positions)
{
    extern __shared__ float sm[];
    unsigned* Qs  = (unsigned*)sm;
    unsigned* Ks  = (unsigned*)(sm + 8448);
    unsigned* Vs  = (unsigned*)(sm + 16896);
    int*      PKs = (int*)(sm + 25344);
    unsigned* Ps  = Ks;               // alias (Ks dead once S is computed)

    const int n    = blockIdx.y;
    const int kh   = n >> 2;
    const int t0   = blockIdx.x * 64;
    const int tid  = threadIdx.x;
    const int lane = tid & 31;
    const int w    = tid >> 5;
    const int g    = lane >> 2;
    const int t    = lane & 3;

    const unsigned* Qg = g_Q + ((size_t)n * TSEQ + t0) * HD;
    for (int i = tid; i < 2048; i += 128) {
        int r = i >> 5, c = (i & 31) << 2;
        *(uint4*)(Qs + r * 132 + c) = *(const uint4*)(Qg + (size_t)r * HD + c);
    }

    const int row0 = w * 16 + g;
    const int pq0 = positions[t0 + row0];
    const int pq1 = positions[t0 + row0 + 8];

    float m0 = -1e30f, m1 = -1e30f, l0 = 0.f, l1 = 0.f;
    float o[16][4];
#pragma unroll
    for (int nt = 0; nt < 16; nt++)
#pragma unroll
        for (int i = 0; i < 4; i++) o[nt][i] = 0.f;

    const unsigned* Kg = g_K + (size_t)kh * TSEQ * HD;
    const unsigned* Vg = g_V + (size_t)kh * TSEQ * HD;

    const int nchunks = blockIdx.x + 1;
    for (int ch = 0; ch < nchunks; ch++) {
        const int s0 = ch * 64;
        __syncthreads();

        for (int i = tid; i < 2048; i += 128) {
            int r = i >> 5, c = (i & 31) << 2;
            *(uint4*)(Ks + r * 132 + c) = *(const uint4*)(Kg + (size_t)(s0 + r) * HD + c);
            *(uint4*)(Vs + r * 132 + c) = *(const uint4*)(Vg + (size_t)(s0 + r) * HD + c);
        }
        if (tid < 64) PKs[tid] = positions[s0 + tid];
        __syncthreads();

        // ---- S = Q K^T (64x64), single-pass tf32 ----
        float s[8][4];
#pragma unroll
        for (int nt = 0; nt < 8; nt++)
#pragma unroll
            for (int i = 0; i < 4; i++) s[nt][i] = 0.f;

#pragma unroll
        for (int ks = 0; ks < 16; ks++) {
            const int k0 = ks * 8;
            const unsigned* qp = Qs + row0 * 132 + k0;
            unsigned a[4] = {qp[t], qp[8 * 132 + t], qp[t + 4], qp[8 * 132 + t + 4]};
#pragma unroll
            for (int nt = 0; nt < 8; nt++) {
                const unsigned* kp = Ks + (nt * 8 + g) * 132 + k0;
                unsigned bb[2] = {kp[t], kp[t + 4]};
                mma_tf32(s[nt], a, bb);
            }
        }

        // ---- mask + online softmax ----
        float mx0 = -1e30f, mx1 = -1e30f;
#pragma unroll
        for (int nt = 0; nt < 8; nt++) {
            const int col = nt * 8 + 2 * t;
            int2 pk = *(const int2*)(PKs + col);
            if (pq0 < pk.x) s[nt][0] = -1e30f;
            if (pq0 < pk.y) s[nt][1] = -1e30f;
            if (pq1 < pk.x) s[nt][2] = -1e30f;
            if (pq1 < pk.y) s[nt][3] = -1e30f;
            mx0 = fmaxf(mx0, fmaxf(s[nt][0], s[nt][1]));
            mx1 = fmaxf(mx1, fmaxf(s[nt][2], s[nt][3]));
        }
        mx0 = fmaxf(mx0, __shfl_xor_sync(0xffffffffu, mx0, 1));
        mx0 = fmaxf(mx0, __shfl_xor_sync(0xffffffffu, mx0, 2));
        mx1 = fmaxf(mx1, __shfl_xor_sync(0xffffffffu, mx1, 1));
        mx1 = fmaxf(mx1, __shfl_xor_sync(0xffffffffu, mx1, 2));

        const float mn0 = fmaxf(m0, mx0), mn1 = fmaxf(m1, mx1);
        const float c0 = __expf(m0 - mn0), c1 = __expf(m1 - mn1);
        m0 = mn0; m1 = mn1;

        float sum0 = 0.f, sum1 = 0.f;
#pragma unroll
        for (int nt = 0; nt < 8; nt++) {
            s[nt][0] = __expf(s[nt][0] - mn0);
            s[nt][1] = __expf(s[nt][1] - mn0);
            s[nt][2] = __expf(s[nt][2] - mn1);
            s[nt][3] = __expf(s[nt][3] - mn1);
            sum0 += s[nt][0] + s[nt][1];
            sum1 += s[nt][2] + s[nt][3];
        }
        sum0 += __shfl_xor_sync(0xffffffffu, sum0, 1);
        sum0 += __shfl_xor_sync(0xffffffffu, sum0, 2);
        sum1 += __shfl_xor_sync(0xffffffffu, sum1, 1);
        sum1 += __shfl_xor_sync(0xffffffffu, sum1, 2);
        l0 = l0 * c0 + sum0;
        l1 = l1 * c1 + sum1;

#pragma unroll
        for (int nt = 0; nt < 16; nt++) {
            o[nt][0] *= c0; o[nt][1] *= c0;
            o[nt][2] *= c1; o[nt][3] *= c1;
        }

        __syncthreads();   // all warps done reading Ks before Ps overwrite

#pragma unroll
        for (int nt = 0; nt < 8; nt++) {
            const int col = nt * 8 + 2 * t;
            uint2 p01 = {f2tf(s[nt][0]), f2tf(s[nt][1])};
            uint2 p23 = {f2tf(s[nt][2]), f2tf(s[nt][3])};
            *(uint2*)(Ps + row0 * 68 + col)       = p01;
            *(uint2*)(Ps + (row0 + 8) * 68 + col) = p23;
        }
        __syncwarp();

#pragma unroll
        for (int ks = 0; ks < 8; ks++) {
            const int k0 = ks * 8;
            const unsigned* pp = Ps + row0 * 68 + k0;
            unsigned a[4] = {pp[t], pp[8 * 68 + t], pp[t + 4], pp[8 * 68 + t + 4]};
#pragma unroll
            for (int nt = 0; nt < 16; nt++) {
                const unsigned* vp = Vs + (k0 + t) * 132 + nt * 8 + g;
                unsigned bb[2] = {vp[0], vp[4 * 132]};
                mma_tf32(o[nt], a, bb);
            }
        }
    }

    // ---- epilogue: write fp16 (feeds k_gemm_o's A side directly) ----
    const float inv0 = 1.f / l0, inv1 = 1.f / l1;
    __half* outr0 = g_A2h + (size_t)(t0 + row0) * DDIM + n * HD;
    __half* outr1 = g_A2h + (size_t)(t0 + row0 + 8) * DDIM + n * HD;
#pragma unroll
    for (int nt = 0; nt < 16; nt++) {
        const int col = nt * 8 + 2 * t;
        *(__half2*)(outr0 + col) = __floats2half2_rn(o[nt][0] * inv0, o[nt][1] * inv0);
        *(__half2*)(outr1 + col) = __floats2half2_rn(o[nt][2] * inv1, o[nt][3] * inv1);
    }
}

// ---------------- kernel 4: output projection ------------------------------
__global__ __launch_bounds__(128) void k_gemm_o(float* __restrict__ out_o)
{
    gemm_mma128_h(g_A2h, DDIM, g_Wp + WOP_OFF + (size_t)blockIdx.x * 128, DDIM,
                  out_o + (size_t)blockIdx.x * 128, DDIM,
                  DDIM, blockIdx.y * 128);
}

// ---------------- launch ----------------------------------------------------
extern "C" void kernel_launch(void* const* d_in, const int* in_sizes, int n_in,
                              void* d_out, int out_size)
{
    (void)in_sizes; (void)n_in; (void)out_size;
    const float* x     = (const float*)d_in[0];
    const float* wq    = (const float*)d_in[1];
    const float* wk    = (const float*)d_in[2];
    const float* wv    = (const float*)d_in[3];
    const float* wo    = (const float*)d_in[4];
    const float* kc_in = (const float*)d_in[5];
    const float* vc_in = (const float*)d_in[6];
    const int* positions = (const int*)d_in[7];
    const int* widx      = (const int*)d_in[8];

    float* out_kc = (float*)d_out;
    float* out_vc = out_kc + (size_t)NSLOTS * NKV * HD;
    float* out_o  = out_vc + (size_t)NSLOTS * NKV * HD;

    static cudaStream_t s2 = nullptr;
    static cudaEvent_t  e1 = nullptr, e2 = nullptr;
    if (!s2) {
        cudaStreamCreateWithFlags(&s2, cudaStreamNonBlocking);
        cudaEventCreateWithFlags(&e1, cudaEventDisableTiming);
        cudaEventCreateWithFlags(&e2, cudaEventDisableTiming);
    }

    const size_t cacheBytes = (size_t)NSLOTS * NKV * HD * sizeof(float);

    // fork: cache copies on s2, concurrent with prep + QKV GEMM
    cudaEventRecord(e1, 0);
    cudaStreamWaitEvent(s2, e1, 0);
    cudaMemcpyAsync(out_kc, kc_in, cacheBytes, cudaMemcpyDeviceToDevice, s2);
    cudaMemcpyAsync(out_vc, vc_in, cacheBytes, cudaMemcpyDeviceToDevice, s2);
    cudaEventRecord(e2, s2);

    // ---- prep: x -> fp16; weights -> packed half2 (along K) ----
    __half* gXh;   cudaGetSymbolAddress((void**)&gXh, g_Xh);
    unsigned* gWp; cudaGetSymbolAddress((void**)&gWp, g_Wp);
    {
        int n4 = (int)((size_t)TSEQ * DDIM / 4);
        k_cvt_half<<<(n4 + 255) / 256, 256>>>((const float4*)x, (uint2*)gXh, n4);

        int nq = (int)WQP_ELEMS;   // K2 = NQ*DDIM/2 rows of N=HD
        k_pack_half<<<(nq + 255) / 256, 256>>>(wq, gWp + WQP_OFF,
                                               NQ * (DDIM / 2), HD);
        int nk = (int)WKP_ELEMS;
        k_pack_half<<<(nk + 255) / 256, 256>>>(wk, gWp + WKP_OFF,
                                               NKV * (DDIM / 2), HD);
        k_pack_half<<<(nk + 255) / 256, 256>>>(wv, gWp + WVP_OFF,
                                               NKV * (DDIM / 2), HD);
        int no = (int)WOP_ELEMS;
        k_pack_half<<<(no + 255) / 256, 256>>>(wo, gWp + WOP_OFF,
                                               DDIM / 2, DDIM);
    }

    k_gemm_qkv<<<dim3(48, TSEQ / 128), 128, 0, 0>>>();

    // join: rope overwrites cache rows, must follow the copies
    cudaStreamWaitEvent(0, e2, 0);
    k_rope<<<TSEQ, 256, 0, 0>>>(positions, widx, out_kc, out_vc);

    const int attn_smem = ATTN2_SMEM_FLOATS * (int)sizeof(float);
    cudaFuncSetAttribute(k_attn_mma,
                         cudaFuncAttributeMaxDynamicSharedMemorySize, attn_smem);
    k_attn_mma<<<dim3(TSEQ / 64, NQ), 128, attn_smem, 0>>>(positions);

    k_gemm_o<<<dim3(DDIM / 128, TSEQ / 128), 128, 0, 0>>>(out_o);
}

// round 10
// speedup vs baseline: 1.9461x; 1.2884x over previous
#include <cuda_runtime.h>
#include <cuda_fp16.h>
#include <cstdint>
#include <stdint.h>
#include <math.h>

// Problem constants (fixed by the dataset)
#define TSEQ   2048
#define DDIM   4096
#define NQ     32
#define NKV    8
#define HD     128
#define NSLOTS 32768
#define QKVC   6144   // 32*128 + 8*128 + 8*128

// Packed-weight offsets (uint = half2 elements), pack along K
#define WQP_ELEMS ((size_t)NQ  * (DDIM / 2) * HD)
#define WKP_ELEMS ((size_t)NKV * (DDIM / 2) * HD)
#define WOP_ELEMS ((size_t)(DDIM / 2) * DDIM)
#define WQP_OFF   ((size_t)0)
#define WKP_OFF   (WQP_OFF + WQP_ELEMS)
#define WVP_OFF   (WKP_OFF + WKP_ELEMS)
#define WOP_OFF   (WVP_OFF + WKP_ELEMS)

// ---------------- scratch (static device allocations; no cudaMalloc) -------
__device__ float    g_QKV[(size_t)TSEQ * QKVC];      // [t][6144] fp32
__device__ __half   g_Qh [(size_t)NQ  * TSEQ * HD];  // [n][t][h] fp16 (scaled)
__device__ __half   g_Kh [(size_t)NKV * TSEQ * HD];  // [kh][t][h] fp16
__device__ unsigned g_Vp [(size_t)NKV * (TSEQ / 2) * HD]; // [kh][t2][h] key-pair half2
__device__ __half   g_A2h[(size_t)TSEQ * DDIM];      // [t][n*128+h] fp16
__device__ __half   g_Xh [(size_t)TSEQ * DDIM];      // x fp16 (A-side)
__device__ unsigned g_Wp [WOP_OFF + WOP_ELEMS];      // packed half2 weights

// ---------------- mma helpers -----------------------------------------------
__device__ __forceinline__ void mma_f16(float* d, const unsigned* a,
                                        const unsigned* b) {
    asm volatile(
        "mma.sync.aligned.m16n8k16.row.col.f32.f16.f16.f32 "
        "{%0,%1,%2,%3}, {%4,%5,%6,%7}, {%8,%9}, {%0,%1,%2,%3};"
        : "+f"(d[0]), "+f"(d[1]), "+f"(d[2]), "+f"(d[3])
        : "r"(a[0]), "r"(a[1]), "r"(a[2]), "r"(a[3]), "r"(b[0]), "r"(b[1]));
}

__device__ __forceinline__ void cp16(unsigned smem, const void* g) {
    asm volatile("cp.async.cg.shared.global [%0], [%1], 16;\n"
                 :: "r"(smem), "l"(g));
}

__device__ __forceinline__ unsigned pack_h2(float a, float b) {
    __half2 h = __floats2half2_rn(a, b);
    return *(unsigned*)&h;
}

// ---------------- prep kernels ---------------------------------------------
__global__ __launch_bounds__(256) void k_cvt_half(
    const float4* __restrict__ in, uint2* __restrict__ out, int n4)
{
    int i = blockIdx.x * 256 + threadIdx.x;
    if (i < n4) {
        float4 v = in[i];
        uint2 o = {pack_h2(v.x, v.y), pack_h2(v.z, v.w)};
        out[i] = o;
    }
}

__global__ __launch_bounds__(256) void k_pack_half(
    const float* __restrict__ in, unsigned* __restrict__ out, int K2, int N)
{
    int i = blockIdx.x * 256 + threadIdx.x;
    if (i < K2 * N) {
        int k2 = i / N, n = i - k2 * N;
        out[i] = pack_h2(in[(size_t)(2 * k2) * N + n],
                         in[(size_t)(2 * k2 + 1) * N + n]);
    }
}

// ---------------- 128x128 fp16 GEMM, 4 warps, 64x64 warp tile --------------
__device__ __forceinline__ void gemm_mma128_h(
    const __half* __restrict__ A, int lda,
    const unsigned* __restrict__ Bp, int ldbp,
    float* __restrict__ C, int ldc,
    int Kdim, int rowBase)
{
    __shared__ unsigned As[3][128][20];
    __shared__ unsigned Bs[3][16][136];

    const int tid  = threadIdx.x;
    const int lane = tid & 31;
    const int warp = tid >> 5;
    const int wM   = warp >> 1;
    const int wN   = warp & 1;
    const int g    = lane >> 2;
    const int t    = lane & 3;

    const int ar = tid >> 2, ac = (tid & 3) << 2;
    const int br = tid >> 5, bc = (tid & 31) << 2;

    const __half* Ab = A + (size_t)rowBase * lda;

    float acc[4][8][4];
#pragma unroll
    for (int mt = 0; mt < 4; mt++)
#pragma unroll
        for (int nt = 0; nt < 8; nt++)
#pragma unroll
            for (int i = 0; i < 4; i++) acc[mt][nt][i] = 0.f;

    const unsigned sA0 = (unsigned)__cvta_generic_to_shared(&As[0][0][0]);
    const unsigned sB0 = (unsigned)__cvta_generic_to_shared(&Bs[0][0][0]);
    const unsigned stASz = (unsigned)(128 * 20 * 4);
    const unsigned stBSz = (unsigned)(16 * 136 * 4);

    const int niter = Kdim >> 5;

#pragma unroll
    for (int p = 0; p < 2; p++) {
        const int k0 = p << 5;
        const int k20 = k0 >> 1;
        const unsigned stA = sA0 + (unsigned)p * stASz;
        const unsigned stB = sB0 + (unsigned)p * stBSz;
#pragma unroll
        for (int q = 0; q < 4; q++) {
            cp16(stA + (unsigned)((ar + q * 32) * 20 + ac) * 4u,
                 Ab + (size_t)(ar + q * 32) * lda + k0 + ac * 2);
            cp16(stB + (unsigned)((br + q * 4) * 136 + bc) * 4u,
                 Bp + (size_t)(k20 + br + q * 4) * ldbp + bc);
        }
        asm volatile("cp.async.commit_group;");
    }

    for (int it = 0; it < niter; it++) {
        asm volatile("cp.async.wait_group 1;");
        __syncthreads();

        if (it + 2 < niter) {
            const int k0 = (it + 2) << 5;
            const int k20 = k0 >> 1;
            const int bsel = (it + 2) % 3;
            const unsigned stA = sA0 + (unsigned)bsel * stASz;
            const unsigned stB = sB0 + (unsigned)bsel * stBSz;
#pragma unroll
            for (int q = 0; q < 4; q++) {
                cp16(stA + (unsigned)((ar + q * 32) * 20 + ac) * 4u,
                     Ab + (size_t)(ar + q * 32) * lda + k0 + ac * 2);
                cp16(stB + (unsigned)((br + q * 4) * 136 + bc) * 4u,
                     Bp + (size_t)(k20 + br + q * 4) * ldbp + bc);
            }
        }
        asm volatile("cp.async.commit_group;");

        const int st = it % 3;
#pragma unroll
        for (int ks = 0; ks < 2; ks++) {
            unsigned af[4][4], bf[8][2];
#pragma unroll
            for (int mt = 0; mt < 4; mt++) {
                const unsigned* p = &As[st][wM * 64 + mt * 16 + g][ks * 8 + t];
                af[mt][0] = p[0];
                af[mt][1] = p[8 * 20];
                af[mt][2] = p[4];
                af[mt][3] = p[8 * 20 + 4];
            }
#pragma unroll
            for (int nt = 0; nt < 8; nt++) {
                bf[nt][0] = Bs[st][ks * 8 + t    ][wN * 64 + nt * 8 + g];
                bf[nt][1] = Bs[st][ks * 8 + t + 4][wN * 64 + nt * 8 + g];
            }
#pragma unroll
            for (int mt = 0; mt < 4; mt++)
#pragma unroll
                for (int nt = 0; nt < 8; nt++)
                    mma_f16(acc[mt][nt], af[mt], bf[nt]);
        }
    }

#pragma unroll
    for (int mt = 0; mt < 4; mt++) {
#pragma unroll
        for (int nt = 0; nt < 8; nt++) {
            const int r0 = rowBase + wM * 64 + mt * 16 + g;
            const int c0 = wN * 64 + nt * 8 + 2 * t;
            float2 v0 = {acc[mt][nt][0], acc[mt][nt][1]};
            float2 v1 = {acc[mt][nt][2], acc[mt][nt][3]};
            *(float2*)(C + (size_t)r0 * ldc + c0)       = v0;
            *(float2*)(C + (size_t)(r0 + 8) * ldc + c0) = v1;
        }
    }
}

// ---------------- kernel 1: fused QKV projection ---------------------------
__global__ __launch_bounds__(128) void k_gemm_qkv()
{
    int cb = blockIdx.x;
    const unsigned* Bp;
    if (cb < 32)      Bp = g_Wp + WQP_OFF + (size_t)cb * (DDIM / 2) * HD;
    else if (cb < 40) Bp = g_Wp + WKP_OFF + (size_t)(cb - 32) * (DDIM / 2) * HD;
    else              Bp = g_Wp + WVP_OFF + (size_t)(cb - 40) * (DDIM / 2) * HD;
    gemm_mma128_h(g_Xh, DDIM, Bp, HD, g_QKV + (size_t)cb * HD, QKVC,
                  DDIM, blockIdx.y * 128);
}

// ---------------- kernel 2: RoPE + fp16 split + cache writeback ------------
__global__ __launch_bounds__(256) void k_rope(
    const int* __restrict__ positions,
    const int* __restrict__ widx,
    float* __restrict__ out_kc,
    float* __restrict__ out_vc)
{
    const int t = blockIdx.x;
    __shared__ float cs[64], sn[64];
    const int pos = positions[t];
    if (threadIdx.x < 64) {
        int i = threadIdx.x;
        double e = -((double)(2 * i) / 128.0);
        float inv = (float)pow(500000.0, e);
        float ang = (float)pos * inv;
        float s, c;
        sincosf(ang, &s, &c);
        cs[i] = c;
        sn[i] = s;
    }
    __syncthreads();

    const float* row = g_QKV + (size_t)t * QKVC;
    const int wi = widx[t];
    const float qscale = 0.08838834764831845f;  // 128^-0.5

    for (int idx = threadIdx.x; idx < NQ * 64; idx += blockDim.x) {
        int n = idx >> 6, i = idx & 63;
        float x1 = row[n * HD + i];
        float x2 = row[n * HD + 64 + i];
        float c = cs[i], s = sn[i];
        __half* qd = g_Qh + ((size_t)n * TSEQ + t) * HD;
        qd[i]      = __float2half((x1 * c - x2 * s) * qscale);
        qd[64 + i] = __float2half((x2 * c + x1 * s) * qscale);
    }
    for (int idx = threadIdx.x; idx < NKV * 64; idx += blockDim.x) {
        int kh = idx >> 6, i = idx & 63;
        float x1 = row[NQ * HD + kh * HD + i];
        float x2 = row[NQ * HD + kh * HD + 64 + i];
        float c = cs[i], s = sn[i];
        float o1 = x1 * c - x2 * s;
        float o2 = x2 * c + x1 * s;
        __half* kd = g_Kh + ((size_t)kh * TSEQ + t) * HD;
        kd[i] = __float2half(o1); kd[64 + i] = __float2half(o2);
        float* kc = out_kc + ((size_t)wi * NKV + kh) * HD;
        kc[i] = o1; kc[64 + i] = o2;    // cache stays exact fp32
    }
    // V: fp16, interleaved along keys (pair t with t^1) for the PV mma k-dim
    for (int idx = threadIdx.x; idx < NKV * HD; idx += blockDim.x) {
        int kh = idx >> 7, h = idx & 127;
        float v = row[(NQ + NKV) * HD + kh * HD + h];
        __half* vh = (__half*)g_Vp;
        vh[(((size_t)kh * (TSEQ / 2) + (t >> 1)) * HD + h) * 2 + (t & 1)] =
            __float2half(v);
        out_vc[((size_t)wi * NKV + kh) * HD + h] = v;   // exact fp32
    }
}

// ---------------- kernel 3: fp16-mma causal flash attention ----------------
// grid = (T/64, NQ), 128 threads (4 warps). Warp w owns query rows w*16..+15.
// All operands fp16 (m16n8k16). smem (uint words):
//   Qs[64][68] @0, Ks[64][68] @4352 (aliased by Ps[64][36]),
//   Vp[32][136] @8704, PKs[64] @13056
#define ATTN3_SMEM_WORDS (4352 * 3 + 64)
__global__ __launch_bounds__(128) void k_attn_h(const int* __restrict__ positions)
{
    extern __shared__ unsigned smw[];
    unsigned* Qs  = smw;
    unsigned* Ks  = smw + 4352;
    unsigned* Vp  = smw + 8704;
    int*      PKs = (int*)(smw + 13056);
    unsigned* Ps  = Ks;               // alias (Ks dead once S is computed)

    const int n    = blockIdx.y;
    const int kh   = n >> 2;
    const int t0   = blockIdx.x * 64;
    const int tid  = threadIdx.x;
    const int lane = tid & 31;
    const int w    = tid >> 5;
    const int g    = lane >> 2;
    const int t    = lane & 3;

    // ---- load Q tile (64 rows x 64 uint) ----
    const unsigned* Qg = (const unsigned*)(g_Qh + ((size_t)n * TSEQ + t0) * HD);
    for (int i = tid; i < 1024; i += 128) {
        int r = i >> 4, c = (i & 15) << 2;
        *(uint4*)(Qs + r * 68 + c) = *(const uint4*)(Qg + (size_t)r * 64 + c);
    }

    const int row0 = w * 16 + g;
    const int pq0 = positions[t0 + row0];
    const int pq1 = positions[t0 + row0 + 8];

    float m0 = -1e30f, m1 = -1e30f, l0 = 0.f, l1 = 0.f;
    float o[16][4];
#pragma unroll
    for (int nt = 0; nt < 16; nt++)
#pragma unroll
        for (int i = 0; i < 4; i++) o[nt][i] = 0.f;

    const unsigned* Kg = (const unsigned*)(g_Kh + (size_t)kh * TSEQ * HD);
    const unsigned* Vg = g_Vp + (size_t)kh * (TSEQ / 2) * HD;

    const int nchunks = blockIdx.x + 1;
    for (int ch = 0; ch < nchunks; ch++) {
        const int s0 = ch * 64;
        __syncthreads();              // prev chunk's Ps/Vp reads done

        for (int i = tid; i < 1024; i += 128) {
            int r = i >> 4, c = (i & 15) << 2;
            *(uint4*)(Ks + r * 68 + c) =
                *(const uint4*)(Kg + (size_t)(s0 + r) * 64 + c);
        }
        for (int i = tid; i < 1024; i += 128) {
            int r2 = i >> 5, c = (i & 31) << 2;
            *(uint4*)(Vp + r2 * 136 + c) =
                *(const uint4*)(Vg + (size_t)(s0 / 2 + r2) * HD + c);
        }
        if (tid < 64) PKs[tid] = positions[s0 + tid];
        __syncthreads();

        // ---- S = Q K^T (64x64), fp16 K16 ----
        float s[8][4];
#pragma unroll
        for (int nt = 0; nt < 8; nt++)
#pragma unroll
            for (int i = 0; i < 4; i++) s[nt][i] = 0.f;

#pragma unroll
        for (int ks = 0; ks < 8; ks++) {
            const unsigned* qp = Qs + row0 * 68 + ks * 8;
            unsigned a[4] = {qp[t], qp[8 * 68 + t], qp[t + 4], qp[8 * 68 + t + 4]};
#pragma unroll
            for (int nt = 0; nt < 8; nt++) {
                const unsigned* kp = Ks + (nt * 8 + g) * 68 + ks * 8;
                unsigned bb[2] = {kp[t], kp[t + 4]};
                mma_f16(s[nt], a, bb);
            }
        }

        // ---- mask + online softmax ----
        float mx0 = -1e30f, mx1 = -1e30f;
#pragma unroll
        for (int nt = 0; nt < 8; nt++) {
            const int col = nt * 8 + 2 * t;
            int2 pk = *(const int2*)(PKs + col);
            if (pq0 < pk.x) s[nt][0] = -1e30f;
            if (pq0 < pk.y) s[nt][1] = -1e30f;
            if (pq1 < pk.x) s[nt][2] = -1e30f;
            if (pq1 < pk.y) s[nt][3] = -1e30f;
            mx0 = fmaxf(mx0, fmaxf(s[nt][0], s[nt][1]));
            mx1 = fmaxf(mx1, fmaxf(s[nt][2], s[nt][3]));
        }
        mx0 = fmaxf(mx0, __shfl_xor_sync(0xffffffffu, mx0, 1));
        mx0 = fmaxf(mx0, __shfl_xor_sync(0xffffffffu, mx0, 2));
        mx1 = fmaxf(mx1, __shfl_xor_sync(0xffffffffu, mx1, 1));
        mx1 = fmaxf(mx1, __shfl_xor_sync(0xffffffffu, mx1, 2));

        const float mn0 = fmaxf(m0, mx0), mn1 = fmaxf(m1, mx1);
        const float c0 = __expf(m0 - mn0), c1 = __expf(m1 - mn1);
        m0 = mn0; m1 = mn1;

        float sum0 = 0.f, sum1 = 0.f;
#pragma unroll
        for (int nt = 0; nt < 8; nt++) {
            s[nt][0] = __expf(s[nt][0] - mn0);
            s[nt][1] = __expf(s[nt][1] - mn0);
            s[nt][2] = __expf(s[nt][2] - mn1);
            s[nt][3] = __expf(s[nt][3] - mn1);
            sum0 += s[nt][0] + s[nt][1];
            sum1 += s[nt][2] + s[nt][3];
        }
        sum0 += __shfl_xor_sync(0xffffffffu, sum0, 1);
        sum0 += __shfl_xor_sync(0xffffffffu, sum0, 2);
        sum1 += __shfl_xor_sync(0xffffffffu, sum1, 1);
        sum1 += __shfl_xor_sync(0xffffffffu, sum1, 2);
        l0 = l0 * c0 + sum0;
        l1 = l1 * c1 + sum1;

#pragma unroll
        for (int nt = 0; nt < 16; nt++) {
            o[nt][0] *= c0; o[nt][1] *= c0;
            o[nt][2] *= c1; o[nt][3] *= c1;
        }

        __syncthreads();   // all warps done reading Ks before Ps overwrite

        // ---- stage P as half2 (thread owns adjacent column pairs) ----
#pragma unroll
        for (int nt = 0; nt < 8; nt++) {
            Ps[row0 * 36 + nt * 4 + t]       = pack_h2(s[nt][0], s[nt][1]);
            Ps[(row0 + 8) * 36 + nt * 4 + t] = pack_h2(s[nt][2], s[nt][3]);
        }
        __syncwarp();

        // ---- O += P V (fp16 K16) ----
#pragma unroll
        for (int ks = 0; ks < 4; ks++) {
            const unsigned* pp = Ps + row0 * 36 + ks * 8;
            unsigned a[4] = {pp[t], pp[8 * 36 + t], pp[t + 4], pp[8 * 36 + t + 4]};
#pragma unroll
            for (int nt = 0; nt < 16; nt++) {
                const unsigned* vp = Vp + (ks * 8 + t) * 136 + nt * 8 + g;
                unsigned bb[2] = {vp[0], vp[4 * 136]};
                mma_f16(o[nt], a, bb);
            }
        }
    }

    // ---- epilogue: write fp16 (feeds k_gemm_o's A side directly) ----
    const float inv0 = 1.f / l0, inv1 = 1.f / l1;
    __half* outr0 = g_A2h + (size_t)(t0 + row0) * DDIM + n * HD;
    __half* outr1 = g_A2h + (size_t)(t0 + row0 + 8) * DDIM + n * HD;
#pragma unroll
    for (int nt = 0; nt < 16; nt++) {
        const int col = nt * 8 + 2 * t;
        *(__half2*)(outr0 + col) = __floats2half2_rn(o[nt][0] * inv0, o[nt][1] * inv0);
        *(__half2*)(outr1 + col) = __floats2half2_rn(o[nt][2] * inv1, o[nt][3] * inv1);
    }
}

// ---------------- kernel 4: output projection ------------------------------
__global__ __launch_bounds__(128) void k_gemm_o(float* __restrict__ out_o)
{
    gemm_mma128_h(g_A2h, DDIM, g_Wp + WOP_OFF + (size_t)blockIdx.x * 128, DDIM,
                  out_o + (size_t)blockIdx.x * 128, DDIM,
                  DDIM, blockIdx.y * 128);
}

// ---------------- launch ----------------------------------------------------
extern "C" void kernel_launch(void* const* d_in, const int* in_sizes, int n_in,
                              void* d_out, int out_size)
{
    (void)in_sizes; (void)n_in; (void)out_size;
    const float* x     = (const float*)d_in[0];
    const float* wq    = (const float*)d_in[1];
    const float* wk    = (const float*)d_in[2];
    const float* wv    = (const float*)d_in[3];
    const float* wo    = (const float*)d_in[4];
    const float* kc_in = (const float*)d_in[5];
    const float* vc_in = (const float*)d_in[6];
    const int* positions = (const int*)d_in[7];
    const int* widx      = (const int*)d_in[8];

    float* out_kc = (float*)d_out;
    float* out_vc = out_kc + (size_t)NSLOTS * NKV * HD;
    float* out_o  = out_vc + (size_t)NSLOTS * NKV * HD;

    static cudaStream_t s2 = nullptr;
    static cudaEvent_t  e1 = nullptr, e2 = nullptr;
    if (!s2) {
        cudaStreamCreateWithFlags(&s2, cudaStreamNonBlocking);
        cudaEventCreateWithFlags(&e1, cudaEventDisableTiming);
        cudaEventCreateWithFlags(&e2, cudaEventDisableTiming);
    }

    const size_t cacheBytes = (size_t)NSLOTS * NKV * HD * sizeof(float);

    // fork: cache copies on s2, concurrent with prep + QKV GEMM
    cudaEventRecord(e1, 0);
    cudaStreamWaitEvent(s2, e1, 0);
    cudaMemcpyAsync(out_kc, kc_in, cacheBytes, cudaMemcpyDeviceToDevice, s2);
    cudaMemcpyAsync(out_vc, vc_in, cacheBytes, cudaMemcpyDeviceToDevice, s2);
    cudaEventRecord(e2, s2);

    // ---- prep: x -> fp16; weights -> packed half2 (along K) ----
    __half* gXh;   cudaGetSymbolAddress((void**)&gXh, g_Xh);
    unsigned* gWp; cudaGetSymbolAddress((void**)&gWp, g_Wp);
    {
        int n4 = (int)((size_t)TSEQ * DDIM / 4);
        k_cvt_half<<<(n4 + 255) / 256, 256>>>((const float4*)x, (uint2*)gXh, n4);

        int nq = (int)WQP_ELEMS;
        k_pack_half<<<(nq + 255) / 256, 256>>>(wq, gWp + WQP_OFF,
                                               NQ * (DDIM / 2), HD);
        int nk = (int)WKP_ELEMS;
        k_pack_half<<<(nk + 255) / 256, 256>>>(wk, gWp + WKP_OFF,
                                               NKV * (DDIM / 2), HD);
        k_pack_half<<<(nk + 255) / 256, 256>>>(wv, gWp + WVP_OFF,
                                               NKV * (DDIM / 2), HD);
        int no = (int)WOP_ELEMS;
        k_pack_half<<<(no + 255) / 256, 256>>>(wo, gWp + WOP_OFF,
                                               DDIM / 2, DDIM);
    }

    k_gemm_qkv<<<dim3(48, TSEQ / 128), 128, 0, 0>>>();

    // join: rope overwrites cache rows, must follow the copies
    cudaStreamWaitEvent(0, e2, 0);
    k_rope<<<TSEQ, 256, 0, 0>>>(positions, widx, out_kc, out_vc);

    const int attn_smem = ATTN3_SMEM_WORDS * (int)sizeof(unsigned);
    cudaFuncSetAttribute(k_attn_h,
                         cudaFuncAttributeMaxDynamicSharedMemorySize, attn_smem);
    k_attn_h<<<dim3(TSEQ / 64, NQ), 128, attn_smem, 0>>>(positions);

    k_gemm_o<<<dim3(DDIM / 128, TSEQ / 128), 128, 0, 0>>>(out_o);
}